// round 6
// baseline (speedup 1.0000x reference)
#include <cuda_runtime.h>
#include <cstdint>
#include <math.h>

#define B_  32
#define S_  2048
#define D_  512
#define M_TOTAL (B_ * S_)

// Gate logit partial sums (device global scratch; zeroed each launch).
__device__ float g_logit[M_TOTAL];

// ---------------------------------------------------------------------------
// helpers
// ---------------------------------------------------------------------------
__device__ __forceinline__ uint32_t smem_u32(const void* p) {
    uint32_t a;
    asm("{ .reg .u64 t; cvta.to.shared.u64 t, %1; cvt.u32.u64 %0, t; }" : "=r"(a) : "l"(p));
    return a;
}
__device__ __forceinline__ uint32_t f2tf32(float f) {
    uint32_t u; asm("cvt.rna.tf32.f32 %0, %1;" : "=r"(u) : "f"(f)); return u;
}
__device__ __forceinline__ void mma_tf32(float* c, const uint32_t* a, uint32_t b0, uint32_t b1) {
    asm volatile(
        "mma.sync.aligned.m16n8k8.row.col.f32.tf32.tf32.f32 "
        "{%0,%1,%2,%3}, {%4,%5,%6,%7}, {%8,%9}, {%0,%1,%2,%3};"
        : "+f"(c[0]), "+f"(c[1]), "+f"(c[2]), "+f"(c[3])
        : "r"(a[0]), "r"(a[1]), "r"(a[2]), "r"(a[3]), "r"(b0), "r"(b1));
}
__device__ __forceinline__ void lds64(uint32_t a, uint32_t& x, uint32_t& y) {
    asm volatile("ld.shared.v2.b32 {%0,%1}, [%2];" : "=r"(x), "=r"(y) : "r"(a));
}
__device__ __forceinline__ void sts128(uint32_t a, uint32_t x, uint32_t y, uint32_t z, uint32_t w) {
    asm volatile("st.shared.v4.b32 [%0], {%1,%2,%3,%4};"
                 :: "r"(a), "r"(x), "r"(y), "r"(z), "r"(w) : "memory");
}

// One "cell" = 32 bytes of a 128x32 tile: row r (0..127), 8-col group grp (0..3).
struct Cell { float4 lo, hi; };

__device__ __forceinline__ Cell ldCell(const float* __restrict__ gp, int r, int grp) {
    Cell c;
    const float4* p = reinterpret_cast<const float4*>(gp + (size_t)r * D_ + grp * 8);
    c.lo = __ldg(p); c.hi = __ldg(p + 1);
    return c;
}

// Conflict-free permuted layout (proven in R5):
//   128B per row; logical k-pair (kk, t) (cols kk*8+t, kk*8+t+4) stored at
//   8B slot (kk ^ (r&3))*4 + t.  Fragment lds64 for fixed (kk,t) tiles all 16
//   slots bijectively per half-warp. STS.128 with even/odd half-order parity.
__device__ __forceinline__ void stCell(uint32_t tile, int r, int grp, const Cell& c, int par) {
    uint32_t base = tile + (uint32_t)(r * 128) + (uint32_t)(((grp ^ (r & 3)) & 3) * 32);
    uint32_t h0x = f2tf32(c.lo.x), h0y = f2tf32(c.hi.x), h0z = f2tf32(c.lo.y), h0w = f2tf32(c.hi.y);
    uint32_t h1x = f2tf32(c.lo.z), h1y = f2tf32(c.hi.z), h1z = f2tf32(c.lo.w), h1w = f2tf32(c.hi.w);
    uint32_t aFirst  = base + (uint32_t)(par << 4);
    uint32_t aSecond = base + (uint32_t)(16 - (par << 4));
    uint32_t fx = par ? h1x : h0x, fy = par ? h1y : h0y, fz = par ? h1z : h0z, fw = par ? h1w : h0w;
    uint32_t sx = par ? h0x : h1x, sy = par ? h0y : h1y, sz = par ? h0z : h1z, sw = par ? h0w : h1w;
    sts128(aFirst,  fx, fy, fz, fw);
    sts128(aSecond, sx, sy, sz, sw);
}

// Common geometry: 1024 threads, 128x128 CTA tile, warp grid 8m x 4n,
// warp tile 16x32 (m16n8k8 x 4ni). 2-stage smem: A 16KB + B 16KB per stage.
#define STAGE_BYTES 32768
#define SMEM_TOT    (STAGE_BYTES * 2)

// Per-thread staging role: threads 0..511 stage tile A, 512..1023 stage tile B.
// Each thread owns one 32B cell per chunk.

// Main-loop macro body shared by the three GEMM kernels.
// Produces accumulators cc[4][4]. gA = A-slab base (row0 applied),
// gB = B base (n0 applied). Both stride D_.
#define GEMM_MAINLOOP(cc)                                                     \
    const int r_   = (tid >> 2) & 127;                                        \
    const int grp_ = tid & 3;                                                 \
    const int par_ = tid & 1;                                                 \
    const bool isA_ = tid < 512;                                              \
    const float* gsrc_ = isA_ ? gA : gB;                                      \
    const uint32_t dTile_ = sb + (isA_ ? 0u : 16384u);                        \
    const uint32_t aB_ = sb + (uint32_t)((wm * 16 + g) * 128);                \
    const uint32_t bB_ = sb + 16384u + (uint32_t)((wn * 32 + g) * 128);       \
    const int g3_ = g & 3;                                                    \
    Cell cell_ = ldCell(gsrc_, r_, grp_);                                     \
    stCell(dTile_, r_, grp_, cell_, par_);                                    \
    _Pragma("unroll 1")                                                       \
    for (int c = 0; c < 16; c++) {                                            \
        __syncthreads();                                                      \
        if (c < 15) cell_ = ldCell(gsrc_ + (c + 1) * 32, r_, grp_);           \
        const uint32_t so_ = (uint32_t)(c & 1) * STAGE_BYTES;                 \
        _Pragma("unroll")                                                     \
        for (int kk = 0; kk < 4; kk++) {                                      \
            const uint32_t co_ = (uint32_t)(((kk ^ g3_) * 32) + t * 8);       \
            uint32_t a_[4];                                                   \
            lds64(aB_ + so_ + co_,        a_[0], a_[2]);                      \
            lds64(aB_ + so_ + 1024 + co_, a_[1], a_[3]);                      \
            _Pragma("unroll")                                                 \
            for (int ni = 0; ni < 4; ni++) {                                  \
                uint32_t b0_, b1_;                                            \
                lds64(bB_ + so_ + (uint32_t)(ni * 1024) + co_, b0_, b1_);     \
                mma_tf32(cc[ni], a_, b0_, b1_);                               \
            }                                                                 \
        }                                                                     \
        if (c < 15) stCell(dTile_ + ((uint32_t)((c + 1) & 1) * STAGE_BYTES),  \
                           r_, grp_, cell_, par_);                            \
    }

// ---------------------------------------------------------------------------
// Kernel 1: gate GEMM  (old_x @ W1^T), fused relu/+old_x/.W2 partial epilogue,
// atomic partial logits into g_logit. Grid (4 nt, 512 rt).
// ---------------------------------------------------------------------------
__global__ void __launch_bounds__(1024, 1) k1_gate(
    const float* __restrict__ old_x, const int* __restrict__ lang,
    const float* __restrict__ gW1,  const float* __restrict__ gb1,
    const float* __restrict__ gW2)
{
    extern __shared__ __align__(16) char dsm[];
    const uint32_t sb = smem_u32(dsm);

    const int tid  = threadIdx.x;
    const int wid  = tid >> 5, lane = tid & 31;
    const int g    = lane >> 2, t = lane & 3;
    const int wm   = wid & 7,  wn  = wid >> 3;       // 8m x 4n warp grid

    const int nt   = blockIdx.x;
    const int rt   = blockIdx.y;
    const int row0 = rt * 128;
    const int n0   = nt * 128;
    const int lg   = lang[rt >> 4];

    const float* gA = old_x + (size_t)row0 * D_;
    const float* gB = gW1 + (size_t)lg * D_ * D_ + (size_t)n0 * D_;
    const float* b1l = gb1 + lg * D_;
    const float* W2l = gW2 + lg * D_;

    float cc[4][4];
    #pragma unroll
    for (int ni = 0; ni < 4; ni++)
        #pragma unroll
        for (int r = 0; r < 4; r++) cc[ni][r] = 0.f;

    GEMM_MAINLOOP(cc)

    // Epilogue: relu(+b1) + old_x, dot with W2 -> per-row partial -> shfl
    // reduce over t -> atomicAdd into g_logit.
    const int r0 = row0 + wm * 16 + g;
    const float* ox0 = old_x + (size_t)r0 * D_;
    const float* ox1 = ox0 + 8 * D_;
    float p0 = 0.f, p1 = 0.f;
    #pragma unroll
    for (int ni = 0; ni < 4; ni++) {
        const int e = n0 + wn * 32 + ni * 8 + 2 * t;
        float2 b1v = *reinterpret_cast<const float2*>(b1l + e);
        float2 w2v = *reinterpret_cast<const float2*>(W2l + e);
        float2 o0v = *reinterpret_cast<const float2*>(ox0 + e);
        float2 o1v = *reinterpret_cast<const float2*>(ox1 + e);
        p0 += (fmaxf(cc[ni][0] + b1v.x, 0.f) + o0v.x) * w2v.x
            + (fmaxf(cc[ni][1] + b1v.y, 0.f) + o0v.y) * w2v.y;
        p1 += (fmaxf(cc[ni][2] + b1v.x, 0.f) + o1v.x) * w2v.x
            + (fmaxf(cc[ni][3] + b1v.y, 0.f) + o1v.y) * w2v.y;
    }
    p0 += __shfl_xor_sync(0xFFFFFFFFu, p0, 1);
    p0 += __shfl_xor_sync(0xFFFFFFFFu, p0, 2);
    p1 += __shfl_xor_sync(0xFFFFFFFFu, p1, 1);
    p1 += __shfl_xor_sync(0xFFFFFFFFu, p1, 2);
    if (t == 0) {
        atomicAdd(&g_logit[r0],     p0);
        atomicAdd(&g_logit[r0 + 8], p1);
    }
}

// ---------------------------------------------------------------------------
// Kernel 2a: share GEMM (x @ shareW^T) -> out (raw). Grid (4 nt, 512 rt).
// ---------------------------------------------------------------------------
__global__ void __launch_bounds__(1024, 1) k2_share(
    const float* __restrict__ x, const float* __restrict__ shareW,
    float* __restrict__ out)
{
    extern __shared__ __align__(16) char dsm[];
    const uint32_t sb = smem_u32(dsm);

    const int tid  = threadIdx.x;
    const int wid  = tid >> 5, lane = tid & 31;
    const int g    = lane >> 2, t = lane & 3;
    const int wm   = wid & 7,  wn  = wid >> 3;

    const int nt   = blockIdx.x;
    const int rt   = blockIdx.y;
    const int row0 = rt * 128;
    const int n0   = nt * 128;

    const float* gA = x + (size_t)row0 * D_;
    const float* gB = shareW + (size_t)n0 * D_;

    float cc[4][4];
    #pragma unroll
    for (int ni = 0; ni < 4; ni++)
        #pragma unroll
        for (int r = 0; r < 4; r++) cc[ni][r] = 0.f;

    GEMM_MAINLOOP(cc)

    const int r0 = row0 + wm * 16 + g;
    float* o0 = out + (size_t)r0 * D_ + n0 + wn * 32;
    float* o1 = o0 + 8 * D_;
    #pragma unroll
    for (int ni = 0; ni < 4; ni++) {
        *reinterpret_cast<float2*>(o0 + ni * 8 + 2 * t) = make_float2(cc[ni][0], cc[ni][1]);
        *reinterpret_cast<float2*>(o1 + ni * 8 + 2 * t) = make_float2(cc[ni][2], cc[ni][3]);
    }
}

// ---------------------------------------------------------------------------
// Kernel 2b: langs GEMM (x @ Wl^T) + blend epilogue:
//   gv = sigmoid(g_logit + b2);  out = out*(1-gv) + langs*gv
// ---------------------------------------------------------------------------
__global__ void __launch_bounds__(1024, 1) k2_lang(
    const float* __restrict__ x, const int* __restrict__ lang,
    const float* __restrict__ langsW, const float* __restrict__ gb2,
    float* __restrict__ out)
{
    extern __shared__ __align__(16) char dsm[];
    const uint32_t sb = smem_u32(dsm);

    const int tid  = threadIdx.x;
    const int wid  = tid >> 5, lane = tid & 31;
    const int g    = lane >> 2, t = lane & 3;
    const int wm   = wid & 7,  wn  = wid >> 3;

    const int nt   = blockIdx.x;
    const int rt   = blockIdx.y;
    const int row0 = rt * 128;
    const int n0   = nt * 128;
    const int lg   = lang[rt >> 4];

    const float* gA = x + (size_t)row0 * D_;
    const float* gB = langsW + (size_t)lg * D_ * D_ + (size_t)n0 * D_;
    const float bb2 = gb2[lg];

    float cc[4][4];
    #pragma unroll
    for (int ni = 0; ni < 4; ni++)
        #pragma unroll
        for (int r = 0; r < 4; r++) cc[ni][r] = 0.f;

    GEMM_MAINLOOP(cc)

    const int r0 = row0 + wm * 16 + g;
    const float gv0 = 1.f / (1.f + expf(-(g_logit[r0]     + bb2)));
    const float gv1 = 1.f / (1.f + expf(-(g_logit[r0 + 8] + bb2)));
    const float n0v = 1.f - gv0, n1v = 1.f - gv1;
    float* o0 = out + (size_t)r0 * D_ + n0 + wn * 32;
    float* o1 = o0 + 8 * D_;
    #pragma unroll
    for (int ni = 0; ni < 4; ni++) {
        float2 s0 = *reinterpret_cast<float2*>(o0 + ni * 8 + 2 * t);
        float2 s1 = *reinterpret_cast<float2*>(o1 + ni * 8 + 2 * t);
        float2 v0 = make_float2(s0.x * n0v + cc[ni][0] * gv0,
                                s0.y * n0v + cc[ni][1] * gv0);
        float2 v1 = make_float2(s1.x * n1v + cc[ni][2] * gv1,
                                s1.y * n1v + cc[ni][3] * gv1);
        *reinterpret_cast<float2*>(o0 + ni * 8 + 2 * t) = v0;
        *reinterpret_cast<float2*>(o1 + ni * 8 + 2 * t) = v1;
    }
}

// ---------------------------------------------------------------------------
// launch
// ---------------------------------------------------------------------------
extern "C" void kernel_launch(void* const* d_in, const int* in_sizes, int n_in,
                              void* d_out, int out_size)
{
    const float* old_x  = (const float*)d_in[0];
    const float* x      = (const float*)d_in[1];
    const int*   lang   = (const int*)  d_in[2];
    const float* shareW = (const float*)d_in[3];
    const float* langsW = (const float*)d_in[4];
    const float* gW1    = (const float*)d_in[5];
    const float* gb1    = (const float*)d_in[6];
    const float* gW2    = (const float*)d_in[7];
    const float* gb2    = (const float*)d_in[8];
    float* out = (float*)d_out;

    cudaFuncSetAttribute(k1_gate,  cudaFuncAttributeMaxDynamicSharedMemorySize, SMEM_TOT);
    cudaFuncSetAttribute(k2_share, cudaFuncAttributeMaxDynamicSharedMemorySize, SMEM_TOT);
    cudaFuncSetAttribute(k2_lang,  cudaFuncAttributeMaxDynamicSharedMemorySize, SMEM_TOT);

    void* logit_ptr = nullptr;
    cudaGetSymbolAddress(&logit_ptr, g_logit);
    cudaMemsetAsync(logit_ptr, 0, M_TOTAL * sizeof(float));

    dim3 grid(D_ / 128, M_TOTAL / 128);
    k1_gate <<<grid, 1024, SMEM_TOT>>>(old_x, lang, gW1, gb1, gW2);
    k2_share<<<grid, 1024, SMEM_TOT>>>(x, shareW, out);
    k2_lang <<<grid, 1024, SMEM_TOT>>>(x, lang, langsW, gb2, out);
}

// round 7
// speedup vs baseline: 1.4538x; 1.4538x over previous
#include <cuda_runtime.h>
#include <cstdint>
#include <math.h>

#define B_  32
#define S_  2048
#define D_  512
#define M_TOTAL (B_ * S_)

// Device scratch (allocation-free): gate logits + RNA-canonical tf32 weights.
__device__ float    g_logit[M_TOTAL];
__device__ uint32_t g_Ws[D_ * D_];
__device__ uint32_t g_Wl[8 * D_ * D_];
__device__ uint32_t g_W1[8 * D_ * D_];

// ---------------------------------------------------------------------------
// helpers
// ---------------------------------------------------------------------------
__device__ __forceinline__ uint32_t smem_u32(const void* p) {
    uint32_t a;
    asm("{ .reg .u64 t; cvta.to.shared.u64 t, %1; cvt.u32.u64 %0, t; }" : "=r"(a) : "l"(p));
    return a;
}
__device__ __forceinline__ uint32_t f2tf32(float f) {
    uint32_t u; asm("cvt.rna.tf32.f32 %0, %1;" : "=r"(u) : "f"(f)); return u;
}
__device__ __forceinline__ void mma_tf32(float* c, const uint32_t* a, uint32_t b0, uint32_t b1) {
    asm volatile(
        "mma.sync.aligned.m16n8k8.row.col.f32.tf32.tf32.f32 "
        "{%0,%1,%2,%3}, {%4,%5,%6,%7}, {%8,%9}, {%0,%1,%2,%3};"
        : "+f"(c[0]), "+f"(c[1]), "+f"(c[2]), "+f"(c[3])
        : "r"(a[0]), "r"(a[1]), "r"(a[2]), "r"(a[3]), "r"(b0), "r"(b1));
}
__device__ __forceinline__ uint32_t lds32(uint32_t a) {
    uint32_t v; asm volatile("ld.shared.b32 %0, [%1];" : "=r"(v) : "r"(a)); return v;
}

#define CP16(d, s)  asm volatile("cp.async.cg.shared.global [%0], [%1], 16;" :: "r"(d), "l"(s))
#define CPCOMMIT()  asm volatile("cp.async.commit_group;" ::: "memory")
#define CPWAIT1()   asm volatile("cp.async.wait_group 1;" ::: "memory")

// ---------------------------------------------------------------------------
// Weight conversion: fp32 -> RNA-canonical tf32 bit patterns (one pass).
// f4-granular; total f4 = 65536 (Ws) + 524288 (Wl) + 524288 (W1) = 1114112.
// ---------------------------------------------------------------------------
__global__ void __launch_bounds__(256) kconv(
    const float* __restrict__ Ws, const float* __restrict__ Wl,
    const float* __restrict__ W1)
{
    int i = blockIdx.x * 256 + threadIdx.x;
    const int NWS = D_ * D_ / 4;
    const int NWL = 8 * D_ * D_ / 4;
    const float4* src; uint4* dst; int j;
    if (i < NWS)            { src = (const float4*)Ws; dst = (uint4*)g_Ws; j = i; }
    else if (i < NWS + NWL) { src = (const float4*)Wl; dst = (uint4*)g_Wl; j = i - NWS; }
    else                    { src = (const float4*)W1; dst = (uint4*)g_W1; j = i - NWS - NWL; }
    float4 v = src[j];
    uint4 o;
    o.x = f2tf32(v.x); o.y = f2tf32(v.y); o.z = f2tf32(v.z); o.w = f2tf32(v.w);
    dst[j] = o;
}

// ---------------------------------------------------------------------------
// Shared GEMM machinery: 512 threads, 128x128 CTA tile, warp grid 4m x 4n,
// warp tile 32x32 (mi 2 x m16n8k8 x ni 4). 3-stage cp.async pipeline.
// Smem tile layout: natural rows (128B), 16B units XOR-swizzled by (row&7).
// Fragment loads are full-warp bank-conflict-free lds32.
// ---------------------------------------------------------------------------
#define STAGE    32768
#define SMEM_TOT (STAGE * 3)

__device__ __forceinline__ void issue_chunk(
    uint32_t stg, const float* __restrict__ gA, const float* __restrict__ gB,
    int k0, int tid)
{
    #pragma unroll
    for (int j = 0; j < 2; j++) {
        const int idx = tid * 2 + j;
        const int r = idx >> 3, u = idx & 7;
        const uint32_t doff = (uint32_t)(r * 128 + ((u ^ (r & 7)) << 4));
        CP16(stg + doff,          gA + (size_t)r * D_ + k0 + u * 4);
        CP16(stg + 16384u + doff, gB + (size_t)r * D_ + k0 + u * 4);
    }
}

// Mainloop macro: fills cc[2][4][4]. Needs: sb, tid, g, t, wm, wn, gA, gB.
#define GEMM_MAIN(cc)                                                          \
    issue_chunk(sb,          gA, gB, 0,  tid); CPCOMMIT();                     \
    issue_chunk(sb + STAGE,  gA, gB, 32, tid); CPCOMMIT();                     \
    {                                                                          \
        const uint32_t aOff = (uint32_t)((wm * 32 + g) * 128);                 \
        const uint32_t bOff = 16384u + (uint32_t)((wn * 32 + g) * 128);        \
        int s = 0, sI = 2;                                                     \
        _Pragma("unroll 1")                                                    \
        for (int c = 0; c < 16; c++) {                                         \
            CPWAIT1();                                                         \
            __syncthreads();                                                   \
            const uint32_t st = sb + (uint32_t)s * STAGE;                      \
            _Pragma("unroll")                                                  \
            for (int kk = 0; kk < 4; kk++) {                                   \
                const uint32_t o0 = ((uint32_t)((2 * kk)     ^ g) << 4) + t * 4; \
                const uint32_t o1 = ((uint32_t)((2 * kk + 1) ^ g) << 4) + t * 4; \
                uint32_t a[2][4];                                              \
                _Pragma("unroll")                                              \
                for (int mi = 0; mi < 2; mi++) {                               \
                    const uint32_t ar = st + aOff + (uint32_t)(mi * 2048);     \
                    a[mi][0] = lds32(ar + o0);                                 \
                    a[mi][1] = lds32(ar + 1024 + o0);                          \
                    a[mi][2] = lds32(ar + o1);                                 \
                    a[mi][3] = lds32(ar + 1024 + o1);                          \
                }                                                              \
                _Pragma("unroll")                                              \
                for (int ni = 0; ni < 4; ni++) {                               \
                    const uint32_t br = st + bOff + (uint32_t)(ni * 1024);     \
                    const uint32_t b0 = lds32(br + o0);                        \
                    const uint32_t b1 = lds32(br + o1);                        \
                    mma_tf32(cc[0][ni], a[0], b0, b1);                         \
                    mma_tf32(cc[1][ni], a[1], b0, b1);                         \
                }                                                              \
            }                                                                  \
            if (c + 2 < 16)                                                    \
                issue_chunk(sb + (uint32_t)sI * STAGE, gA, gB, (c + 2) * 32, tid); \
            CPCOMMIT();                                                        \
            s  = (s  == 2) ? 0 : s  + 1;                                       \
            sI = (sI == 2) ? 0 : sI + 1;                                       \
        }                                                                      \
    }

#define GEMM_PRELUDE                                                           \
    extern __shared__ __align__(128) char dsm[];                               \
    const uint32_t sb = smem_u32(dsm);                                         \
    const int tid  = threadIdx.x;                                              \
    const int wid  = tid >> 5, lane = tid & 31;                                \
    const int g    = lane >> 2, t = lane & 3;                                  \
    const int wm   = wid & 3,  wn  = wid >> 2;                                 \
    const int nt   = blockIdx.x;                                               \
    const int rt   = blockIdx.y;                                               \
    const int row0 = rt * 128;                                                 \
    const int n0   = nt * 128;                                                 \
    float cc[2][4][4];                                                         \
    _Pragma("unroll")                                                          \
    for (int mi = 0; mi < 2; mi++)                                             \
        _Pragma("unroll")                                                      \
        for (int ni = 0; ni < 4; ni++)                                         \
            _Pragma("unroll")                                                  \
            for (int r = 0; r < 4; r++) cc[mi][ni][r] = 0.f;

// ---------------------------------------------------------------------------
// Kernel 1: gate GEMM (old_x @ W1^T) + fused relu/+old_x/.W2 -> atomic logits.
// ---------------------------------------------------------------------------
__global__ void __launch_bounds__(512, 2) k1_gate(
    const float* __restrict__ old_x, const int* __restrict__ lang,
    const float* __restrict__ gb1,  const float* __restrict__ gW2)
{
    GEMM_PRELUDE
    const int lg = lang[rt >> 4];
    const float* gA = old_x + (size_t)row0 * D_;
    const float* gB = reinterpret_cast<const float*>(g_W1)
                    + (size_t)lg * D_ * D_ + (size_t)n0 * D_;
    const float* b1l = gb1 + lg * D_;
    const float* W2l = gW2 + lg * D_;

    GEMM_MAIN(cc)

    #pragma unroll
    for (int mi = 0; mi < 2; mi++) {
        #pragma unroll
        for (int h = 0; h < 2; h++) {
            const int row = row0 + wm * 32 + mi * 16 + h * 8 + g;
            const float* oxr = old_x + (size_t)row * D_;
            float acc = 0.f;
            #pragma unroll
            for (int ni = 0; ni < 4; ni++) {
                const int e = n0 + wn * 32 + ni * 8 + 2 * t;
                float2 b1v = *reinterpret_cast<const float2*>(b1l + e);
                float2 w2v = *reinterpret_cast<const float2*>(W2l + e);
                float2 oxv = *reinterpret_cast<const float2*>(oxr + e);
                acc += (fmaxf(cc[mi][ni][2 * h]     + b1v.x, 0.f) + oxv.x) * w2v.x
                     + (fmaxf(cc[mi][ni][2 * h + 1] + b1v.y, 0.f) + oxv.y) * w2v.y;
            }
            acc += __shfl_xor_sync(0xFFFFFFFFu, acc, 1);
            acc += __shfl_xor_sync(0xFFFFFFFFu, acc, 2);
            if (t == 0) atomicAdd(&g_logit[row], acc);
        }
    }
}

// ---------------------------------------------------------------------------
// Kernel 2a: share GEMM (x @ shareW^T) -> out raw.
// ---------------------------------------------------------------------------
__global__ void __launch_bounds__(512, 2) k2_share(
    const float* __restrict__ x, float* __restrict__ out)
{
    GEMM_PRELUDE
    const float* gA = x + (size_t)row0 * D_;
    const float* gB = reinterpret_cast<const float*>(g_Ws) + (size_t)n0 * D_;

    GEMM_MAIN(cc)

    #pragma unroll
    for (int mi = 0; mi < 2; mi++) {
        #pragma unroll
        for (int h = 0; h < 2; h++) {
            const int row = row0 + wm * 32 + mi * 16 + h * 8 + g;
            float* o = out + (size_t)row * D_ + n0 + wn * 32;
            #pragma unroll
            for (int ni = 0; ni < 4; ni++)
                *reinterpret_cast<float2*>(o + ni * 8 + 2 * t) =
                    make_float2(cc[mi][ni][2 * h], cc[mi][ni][2 * h + 1]);
        }
    }
}

// ---------------------------------------------------------------------------
// Kernel 2b: langs GEMM (x @ Wl^T) + blend:
//   gv = sigmoid(g_logit + b2);  out = out*(1-gv) + langs*gv
// ---------------------------------------------------------------------------
__global__ void __launch_bounds__(512, 2) k2_lang(
    const float* __restrict__ x, const int* __restrict__ lang,
    const float* __restrict__ gb2, float* __restrict__ out)
{
    GEMM_PRELUDE
    const int lg = lang[rt >> 4];
    const float* gA = x + (size_t)row0 * D_;
    const float* gB = reinterpret_cast<const float*>(g_Wl)
                    + (size_t)lg * D_ * D_ + (size_t)n0 * D_;
    const float bb2 = gb2[lg];

    GEMM_MAIN(cc)

    #pragma unroll
    for (int mi = 0; mi < 2; mi++) {
        #pragma unroll
        for (int h = 0; h < 2; h++) {
            const int row = row0 + wm * 32 + mi * 16 + h * 8 + g;
            const float gv  = 1.f / (1.f + expf(-(g_logit[row] + bb2)));
            const float ngv = 1.f - gv;
            float* o = out + (size_t)row * D_ + n0 + wn * 32;
            #pragma unroll
            for (int ni = 0; ni < 4; ni++) {
                float2 sv = *reinterpret_cast<float2*>(o + ni * 8 + 2 * t);
                *reinterpret_cast<float2*>(o + ni * 8 + 2 * t) =
                    make_float2(sv.x * ngv + cc[mi][ni][2 * h]     * gv,
                                sv.y * ngv + cc[mi][ni][2 * h + 1] * gv);
            }
        }
    }
}

// ---------------------------------------------------------------------------
// launch
// ---------------------------------------------------------------------------
extern "C" void kernel_launch(void* const* d_in, const int* in_sizes, int n_in,
                              void* d_out, int out_size)
{
    const float* old_x  = (const float*)d_in[0];
    const float* x      = (const float*)d_in[1];
    const int*   lang   = (const int*)  d_in[2];
    const float* shareW = (const float*)d_in[3];
    const float* langsW = (const float*)d_in[4];
    const float* gW1    = (const float*)d_in[5];
    const float* gb1    = (const float*)d_in[6];
    const float* gW2    = (const float*)d_in[7];
    const float* gb2    = (const float*)d_in[8];
    float* out = (float*)d_out;

    cudaFuncSetAttribute(k1_gate,  cudaFuncAttributeMaxDynamicSharedMemorySize, SMEM_TOT);
    cudaFuncSetAttribute(k2_share, cudaFuncAttributeMaxDynamicSharedMemorySize, SMEM_TOT);
    cudaFuncSetAttribute(k2_lang,  cudaFuncAttributeMaxDynamicSharedMemorySize, SMEM_TOT);

    void* logit_ptr = nullptr;
    cudaGetSymbolAddress(&logit_ptr, g_logit);
    cudaMemsetAsync(logit_ptr, 0, M_TOTAL * sizeof(float));

    kconv<<<4352, 256>>>(shareW, langsW, gW1);

    dim3 grid(D_ / 128, M_TOTAL / 128);
    k1_gate <<<grid, 512, SMEM_TOT>>>(old_x, lang, gb1, gW2);
    k2_share<<<grid, 512, SMEM_TOT>>>(x, out);
    k2_lang <<<grid, 512, SMEM_TOT>>>(x, lang, gb2, out);
}

// round 8
// speedup vs baseline: 1.6734x; 1.1511x over previous
#include <cuda_runtime.h>
#include <cstdint>
#include <math.h>

#define B_  32
#define S_  2048
#define D_  512
#define M_TOTAL (B_ * S_)

// Device scratch (allocation-free): gate logits + RNA-canonical tf32 weights.
__device__ float    g_logit[M_TOTAL];
__device__ uint32_t g_Ws[D_ * D_];
__device__ uint32_t g_Wl[8 * D_ * D_];
__device__ uint32_t g_W1[8 * D_ * D_];

// ---------------------------------------------------------------------------
// helpers
// ---------------------------------------------------------------------------
__device__ __forceinline__ uint32_t smem_u32(const void* p) {
    uint32_t a;
    asm("{ .reg .u64 t; cvta.to.shared.u64 t, %1; cvt.u32.u64 %0, t; }" : "=r"(a) : "l"(p));
    return a;
}
__device__ __forceinline__ uint32_t f2tf32(float f) {
    uint32_t u; asm("cvt.rna.tf32.f32 %0, %1;" : "=r"(u) : "f"(f)); return u;
}
__device__ __forceinline__ void mma_tf32(float* c, const uint32_t* a, uint32_t b0, uint32_t b1) {
    asm volatile(
        "mma.sync.aligned.m16n8k8.row.col.f32.tf32.tf32.f32 "
        "{%0,%1,%2,%3}, {%4,%5,%6,%7}, {%8,%9}, {%0,%1,%2,%3};"
        : "+f"(c[0]), "+f"(c[1]), "+f"(c[2]), "+f"(c[3])
        : "r"(a[0]), "r"(a[1]), "r"(a[2]), "r"(a[3]), "r"(b0), "r"(b1));
}
__device__ __forceinline__ uint32_t lds32(uint32_t a) {
    uint32_t v; asm volatile("ld.shared.b32 %0, [%1];" : "=r"(v) : "r"(a)); return v;
}

#define CP16(d, s)  asm volatile("cp.async.cg.shared.global [%0], [%1], 16;" :: "r"(d), "l"(s))
#define CPCOMMIT()  asm volatile("cp.async.commit_group;" ::: "memory")
#define CPWAIT1()   asm volatile("cp.async.wait_group 1;" ::: "memory")
#define CPWAIT2()   asm volatile("cp.async.wait_group 2;" ::: "memory")

// ---------------------------------------------------------------------------
// Weight conversion: fp32 -> RNA-canonical tf32 bit patterns (one pass).
// ---------------------------------------------------------------------------
__global__ void __launch_bounds__(256) kconv(
    const float* __restrict__ Ws, const float* __restrict__ Wl,
    const float* __restrict__ W1)
{
    int i = blockIdx.x * 256 + threadIdx.x;
    const int NWS = D_ * D_ / 4;
    const int NWL = 8 * D_ * D_ / 4;
    const float4* src; uint4* dst; int j;
    if (i < NWS)            { src = (const float4*)Ws; dst = (uint4*)g_Ws; j = i; }
    else if (i < NWS + NWL) { src = (const float4*)Wl; dst = (uint4*)g_Wl; j = i - NWS; }
    else                    { src = (const float4*)W1; dst = (uint4*)g_W1; j = i - NWS - NWL; }
    float4 v = src[j];
    uint4 o;
    o.x = f2tf32(v.x); o.y = f2tf32(v.y); o.z = f2tf32(v.z); o.w = f2tf32(v.w);
    dst[j] = o;
}

// ---------------------------------------------------------------------------
// Common: 128x128 CTA tile, 512 threads, warp grid 4m x 4n, warp tile 32x32
// per GEMM. Smem tiles: natural 128B rows, 16B units XOR-swizzled by (row&7).
// Fragment lds32 are full-warp bank-conflict-free (proven R7).
// ---------------------------------------------------------------------------
#define STAGE    32768
#define SMEM_TOT (STAGE * 3)

__device__ __forceinline__ void issue_chunk(
    uint32_t stg, const float* __restrict__ gA, const float* __restrict__ gB,
    int k0, int tid)
{
    #pragma unroll
    for (int j = 0; j < 2; j++) {
        const int idx = tid * 2 + j;
        const int r = idx >> 3, u = idx & 7;
        const uint32_t doff = (uint32_t)(r * 128 + ((u ^ (r & 7)) << 4));
        CP16(stg + doff,          gA + (size_t)r * D_ + k0 + u * 4);
        CP16(stg + 16384u + doff, gB + (size_t)r * D_ + k0 + u * 4);
    }
}

// ---------------------------------------------------------------------------
// Kernel 1: gate GEMM (old_x @ W1^T) + fused relu/+old_x/.W2 -> atomic logits.
// (unchanged from R7: 3-stage cp.async, occupancy 2)
// ---------------------------------------------------------------------------
__global__ void __launch_bounds__(512, 2) k1_gate(
    const float* __restrict__ old_x, const int* __restrict__ lang,
    const float* __restrict__ gb1,  const float* __restrict__ gW2)
{
    extern __shared__ __align__(128) char dsm[];
    const uint32_t sb = smem_u32(dsm);
    const int tid  = threadIdx.x;
    const int wid  = tid >> 5, lane = tid & 31;
    const int g    = lane >> 2, t = lane & 3;
    const int wm   = wid & 3,  wn  = wid >> 2;
    const int nt   = blockIdx.x;
    const int rt   = blockIdx.y;
    const int row0 = rt * 128;
    const int n0   = nt * 128;
    const int lg   = lang[rt >> 4];

    const float* gA = old_x + (size_t)row0 * D_;
    const float* gB = reinterpret_cast<const float*>(g_W1)
                    + (size_t)lg * D_ * D_ + (size_t)n0 * D_;
    const float* b1l = gb1 + lg * D_;
    const float* W2l = gW2 + lg * D_;

    float cc[2][4][4];
    #pragma unroll
    for (int mi = 0; mi < 2; mi++)
        #pragma unroll
        for (int ni = 0; ni < 4; ni++)
            #pragma unroll
            for (int r = 0; r < 4; r++) cc[mi][ni][r] = 0.f;

    issue_chunk(sb,         gA, gB, 0,  tid); CPCOMMIT();
    issue_chunk(sb + STAGE, gA, gB, 32, tid); CPCOMMIT();
    {
        const uint32_t aOff = (uint32_t)((wm * 32 + g) * 128);
        const uint32_t bOff = 16384u + (uint32_t)((wn * 32 + g) * 128);
        int s = 0, sI = 2;
        #pragma unroll 1
        for (int c = 0; c < 16; c++) {
            CPWAIT1();
            __syncthreads();
            const uint32_t st = sb + (uint32_t)s * STAGE;
            #pragma unroll
            for (int kk = 0; kk < 4; kk++) {
                const uint32_t o0 = ((uint32_t)((2 * kk)     ^ g) << 4) + t * 4;
                const uint32_t o1 = ((uint32_t)((2 * kk + 1) ^ g) << 4) + t * 4;
                uint32_t a[2][4];
                #pragma unroll
                for (int mi = 0; mi < 2; mi++) {
                    const uint32_t ar = st + aOff + (uint32_t)(mi * 2048);
                    a[mi][0] = lds32(ar + o0);
                    a[mi][1] = lds32(ar + 1024 + o0);
                    a[mi][2] = lds32(ar + o1);
                    a[mi][3] = lds32(ar + 1024 + o1);
                }
                #pragma unroll
                for (int ni = 0; ni < 4; ni++) {
                    const uint32_t br = st + bOff + (uint32_t)(ni * 1024);
                    const uint32_t b0 = lds32(br + o0);
                    const uint32_t b1 = lds32(br + o1);
                    mma_tf32(cc[0][ni], a[0], b0, b1);
                    mma_tf32(cc[1][ni], a[1], b0, b1);
                }
            }
            if (c + 2 < 16)
                issue_chunk(sb + (uint32_t)sI * STAGE, gA, gB, (c + 2) * 32, tid);
            CPCOMMIT();
            s  = (s  == 2) ? 0 : s  + 1;
            sI = (sI == 2) ? 0 : sI + 1;
        }
    }

    #pragma unroll
    for (int mi = 0; mi < 2; mi++) {
        #pragma unroll
        for (int h = 0; h < 2; h++) {
            const int row = row0 + wm * 32 + mi * 16 + h * 8 + g;
            const float* oxr = old_x + (size_t)row * D_;
            float acc = 0.f;
            #pragma unroll
            for (int ni = 0; ni < 4; ni++) {
                const int e = n0 + wn * 32 + ni * 8 + 2 * t;
                float2 b1v = *reinterpret_cast<const float2*>(b1l + e);
                float2 w2v = *reinterpret_cast<const float2*>(W2l + e);
                float2 oxv = *reinterpret_cast<const float2*>(oxr + e);
                acc += (fmaxf(cc[mi][ni][2 * h]     + b1v.x, 0.f) + oxv.x) * w2v.x
                     + (fmaxf(cc[mi][ni][2 * h + 1] + b1v.y, 0.f) + oxv.y) * w2v.y;
            }
            acc += __shfl_xor_sync(0xFFFFFFFFu, acc, 1);
            acc += __shfl_xor_sync(0xFFFFFFFFu, acc, 2);
            if (t == 0) atomicAdd(&g_logit[row], acc);
        }
    }
}

// ---------------------------------------------------------------------------
// Kernel 2: fused dual GEMM  out = (x@Ws^T)*(1-gv) + (x@Wl^T)*gv,
//           gv = sigmoid(g_logit + b2).
// 512 threads, 1 CTA/SM (128-reg budget -> ptxas pipelines LDS vs HMMA),
// A fragments shared by both B operands, 4-stage cp.async (192KB smem).
// ---------------------------------------------------------------------------
#define STAGE_D   49152
#define SMEM_DUAL (STAGE_D * 4)

__global__ void __launch_bounds__(512, 1) k2_fused(
    const float* __restrict__ x, const int* __restrict__ lang,
    const float* __restrict__ gb2, float* __restrict__ out)
{
    extern __shared__ __align__(128) char dsm[];
    const uint32_t sb = smem_u32(dsm);
    const int tid  = threadIdx.x;
    const int wid  = tid >> 5, lane = tid & 31;
    const int g    = lane >> 2, t = lane & 3;
    const int wm   = wid & 3,  wn  = wid >> 2;
    const int nt   = blockIdx.x;
    const int rt   = blockIdx.y;
    const int row0 = rt * 128;
    const int n0   = nt * 128;
    const int lg   = lang[rt >> 4];

    const float* gA = x + (size_t)row0 * D_;
    const float* gS = reinterpret_cast<const float*>(g_Ws) + (size_t)n0 * D_;
    const float* gL = reinterpret_cast<const float*>(g_Wl)
                    + (size_t)lg * D_ * D_ + (size_t)n0 * D_;
    const float bb2 = gb2[lg];

    float cs[2][4][4], cl[2][4][4];
    #pragma unroll
    for (int mi = 0; mi < 2; mi++)
        #pragma unroll
        for (int ni = 0; ni < 4; ni++)
            #pragma unroll
            for (int r = 0; r < 4; r++) { cs[mi][ni][r] = 0.f; cl[mi][ni][r] = 0.f; }

    // issue one chunk (A + Bs + Bl) into stage
    auto issue3 = [&](uint32_t stg, int k0) {
        #pragma unroll
        for (int j = 0; j < 2; j++) {
            const int idx = tid * 2 + j;
            const int r = idx >> 3, u = idx & 7;
            const uint32_t doff = (uint32_t)(r * 128 + ((u ^ (r & 7)) << 4));
            const size_t goff = (size_t)r * D_ + k0 + u * 4;
            CP16(stg + doff,          gA + goff);
            CP16(stg + 16384u + doff, gS + goff);
            CP16(stg + 32768u + doff, gL + goff);
        }
    };

    issue3(sb,               0);  CPCOMMIT();
    issue3(sb + STAGE_D,     32); CPCOMMIT();
    issue3(sb + 2 * STAGE_D, 64); CPCOMMIT();

    const uint32_t aOff = (uint32_t)((wm * 32 + g) * 128);
    const uint32_t sOff = 16384u + (uint32_t)((wn * 32 + g) * 128);
    const uint32_t lOff = 32768u + (uint32_t)((wn * 32 + g) * 128);

    #pragma unroll 1
    for (int c = 0; c < 16; c++) {
        CPWAIT2();
        __syncthreads();
        const uint32_t st = sb + (uint32_t)(c & 3) * STAGE_D;
        #pragma unroll
        for (int kk = 0; kk < 4; kk++) {
            const uint32_t o0 = ((uint32_t)((2 * kk)     ^ g) << 4) + t * 4;
            const uint32_t o1 = ((uint32_t)((2 * kk + 1) ^ g) << 4) + t * 4;
            uint32_t a[2][4];
            #pragma unroll
            for (int mi = 0; mi < 2; mi++) {
                const uint32_t ar = st + aOff + (uint32_t)(mi * 2048);
                a[mi][0] = lds32(ar + o0);
                a[mi][1] = lds32(ar + 1024 + o0);
                a[mi][2] = lds32(ar + o1);
                a[mi][3] = lds32(ar + 1024 + o1);
            }
            #pragma unroll
            for (int ni = 0; ni < 4; ni++) {
                const uint32_t sr = st + sOff + (uint32_t)(ni * 1024);
                const uint32_t lr = st + lOff + (uint32_t)(ni * 1024);
                const uint32_t s0 = lds32(sr + o0);
                const uint32_t s1 = lds32(sr + o1);
                const uint32_t l0 = lds32(lr + o0);
                const uint32_t l1 = lds32(lr + o1);
                mma_tf32(cs[0][ni], a[0], s0, s1);
                mma_tf32(cs[1][ni], a[1], s0, s1);
                mma_tf32(cl[0][ni], a[0], l0, l1);
                mma_tf32(cl[1][ni], a[1], l0, l1);
            }
        }
        if (c + 3 < 16)
            issue3(sb + (uint32_t)((c + 3) & 3) * STAGE_D, (c + 3) * 32);
        CPCOMMIT();
    }

    // Epilogue: gate blend, float2 stores.
    #pragma unroll
    for (int mi = 0; mi < 2; mi++) {
        #pragma unroll
        for (int h = 0; h < 2; h++) {
            const int row = row0 + wm * 32 + mi * 16 + h * 8 + g;
            const float gv  = 1.f / (1.f + expf(-(g_logit[row] + bb2)));
            const float ngv = 1.f - gv;
            float* o = out + (size_t)row * D_ + n0 + wn * 32;
            #pragma unroll
            for (int ni = 0; ni < 4; ni++) {
                *reinterpret_cast<float2*>(o + ni * 8 + 2 * t) =
                    make_float2(cs[mi][ni][2 * h]     * ngv + cl[mi][ni][2 * h]     * gv,
                                cs[mi][ni][2 * h + 1] * ngv + cl[mi][ni][2 * h + 1] * gv);
            }
        }
    }
}

// ---------------------------------------------------------------------------
// launch
// ---------------------------------------------------------------------------
extern "C" void kernel_launch(void* const* d_in, const int* in_sizes, int n_in,
                              void* d_out, int out_size)
{
    const float* old_x  = (const float*)d_in[0];
    const float* x      = (const float*)d_in[1];
    const int*   lang   = (const int*)  d_in[2];
    const float* shareW = (const float*)d_in[3];
    const float* langsW = (const float*)d_in[4];
    const float* gW1    = (const float*)d_in[5];
    const float* gb1    = (const float*)d_in[6];
    const float* gW2    = (const float*)d_in[7];
    const float* gb2    = (const float*)d_in[8];
    float* out = (float*)d_out;

    cudaFuncSetAttribute(k1_gate,  cudaFuncAttributeMaxDynamicSharedMemorySize, SMEM_TOT);
    cudaFuncSetAttribute(k2_fused, cudaFuncAttributeMaxDynamicSharedMemorySize, SMEM_DUAL);

    void* logit_ptr = nullptr;
    cudaGetSymbolAddress(&logit_ptr, g_logit);
    cudaMemsetAsync(logit_ptr, 0, M_TOTAL * sizeof(float));

    kconv<<<4352, 256>>>(shareW, langsW, gW1);

    dim3 grid(D_ / 128, M_TOTAL / 128);
    k1_gate <<<grid, 512, SMEM_TOT>>>(old_x, lang, gb1, gW2);
    k2_fused<<<grid, 512, SMEM_DUAL>>>(x, lang, gb2, out);
}

// round 9
// speedup vs baseline: 1.7746x; 1.0605x over previous
#include <cuda_runtime.h>
#include <cstdint>
#include <math.h>

#define B_  32
#define S_  2048
#define D_  512
#define M_TOTAL (B_ * S_)

// Device scratch (allocation-free): gate logits + RNA-canonical tf32 weights.
__device__ float    g_logit[M_TOTAL];
__device__ uint32_t g_Ws[D_ * D_];
__device__ uint32_t g_Wl[8 * D_ * D_];
__device__ uint32_t g_W1[8 * D_ * D_];

// ---------------------------------------------------------------------------
// helpers
// ---------------------------------------------------------------------------
__device__ __forceinline__ uint32_t smem_u32(const void* p) {
    uint32_t a;
    asm("{ .reg .u64 t; cvta.to.shared.u64 t, %1; cvt.u32.u64 %0, t; }" : "=r"(a) : "l"(p));
    return a;
}
__device__ __forceinline__ uint32_t f2tf32(float f) {
    uint32_t u; asm("cvt.rna.tf32.f32 %0, %1;" : "=r"(u) : "f"(f)); return u;
}
__device__ __forceinline__ void mma_tf32(float* c, const uint32_t* a, uint32_t b0, uint32_t b1) {
    asm volatile(
        "mma.sync.aligned.m16n8k8.row.col.f32.tf32.tf32.f32 "
        "{%0,%1,%2,%3}, {%4,%5,%6,%7}, {%8,%9}, {%0,%1,%2,%3};"
        : "+f"(c[0]), "+f"(c[1]), "+f"(c[2]), "+f"(c[3])
        : "r"(a[0]), "r"(a[1]), "r"(a[2]), "r"(a[3]), "r"(b0), "r"(b1));
}
__device__ __forceinline__ uint32_t lds32(uint32_t a) {
    uint32_t v; asm volatile("ld.shared.b32 %0, [%1];" : "=r"(v) : "r"(a)); return v;
}

#define CP16(d, s)  asm volatile("cp.async.cg.shared.global [%0], [%1], 16;" :: "r"(d), "l"(s))
#define CPCOMMIT()  asm volatile("cp.async.commit_group;" ::: "memory")
#define CPWAIT2()   asm volatile("cp.async.wait_group 2;" ::: "memory")

// ---------------------------------------------------------------------------
// Weight conversion: fp32 -> RNA-canonical tf32 bit patterns (one pass).
// ---------------------------------------------------------------------------
__global__ void __launch_bounds__(256) kconv(
    const float* __restrict__ Ws, const float* __restrict__ Wl,
    const float* __restrict__ W1)
{
    int i = blockIdx.x * 256 + threadIdx.x;
    const int NWS = D_ * D_ / 4;
    const int NWL = 8 * D_ * D_ / 4;
    const float4* src; uint4* dst; int j;
    if (i < NWS)            { src = (const float4*)Ws; dst = (uint4*)g_Ws; j = i; }
    else if (i < NWS + NWL) { src = (const float4*)Wl; dst = (uint4*)g_Wl; j = i - NWS; }
    else                    { src = (const float4*)W1; dst = (uint4*)g_W1; j = i - NWS - NWL; }
    float4 v = src[j];
    uint4 o;
    o.x = f2tf32(v.x); o.y = f2tf32(v.y); o.z = f2tf32(v.z); o.w = f2tf32(v.w);
    dst[j] = o;
}

// ---------------------------------------------------------------------------
// Kernel 1: gate GEMM (old_x @ W1^T) + fused relu/+old_x/.W2 -> atomic logits.
// NEW geometry: CTA tile 128x256 (A 128 rows, B 256 n-rows), 512 threads,
// warp grid 4m x 4n, warp tile 32x64 (mi 2 x ni 8). occ 1 -> 128-reg budget
// gives ptxas slack to overlap LDS with HMMA. 4-stage cp.async.
// Smem/stage: A 16KB + B 32KB = 48KB; x4 = 192KB.
// ---------------------------------------------------------------------------
#define K1_STAGE 49152
#define K1_SMEM  (K1_STAGE * 4)

__global__ void __launch_bounds__(512, 1) k1_gate(
    const float* __restrict__ old_x, const int* __restrict__ lang,
    const float* __restrict__ gb1,  const float* __restrict__ gW2)
{
    extern __shared__ __align__(128) char dsm[];
    const uint32_t sb = smem_u32(dsm);
    const int tid  = threadIdx.x;
    const int wid  = tid >> 5, lane = tid & 31;
    const int g    = lane >> 2, t = lane & 3;
    const int wm   = wid & 3,  wn  = wid >> 2;       // 4m x 4n, warp tile 32x64
    const int nt   = blockIdx.x;                      // 2 tiles of 256 cols
    const int rt   = blockIdx.y;
    const int row0 = rt * 128;
    const int n0   = nt * 256;
    const int lg   = lang[rt >> 4];

    const float* gA = old_x + (size_t)row0 * D_;
    const float* gB = reinterpret_cast<const float*>(g_W1)
                    + (size_t)lg * D_ * D_ + (size_t)n0 * D_;
    const float* b1l = gb1 + lg * D_;
    const float* W2l = gW2 + lg * D_;

    float cc[2][8][4];
    #pragma unroll
    for (int mi = 0; mi < 2; mi++)
        #pragma unroll
        for (int ni = 0; ni < 8; ni++)
            #pragma unroll
            for (int r = 0; r < 4; r++) cc[mi][ni][r] = 0.f;

    // chunk issue: 1024 A cells + 2048 B cells = 3072; 6 per thread.
    auto issueK1 = [&](uint32_t stg, int k0) {
        #pragma unroll
        for (int j = 0; j < 6; j++) {
            const int idx = j * 512 + tid;
            if (idx < 1024) {
                const int r = idx >> 3, u = idx & 7;
                const uint32_t doff = (uint32_t)(r * 128 + ((u ^ (r & 7)) << 4));
                CP16(stg + doff, gA + (size_t)r * D_ + k0 + u * 4);
            } else {
                const int idx2 = idx - 1024;
                const int r = idx2 >> 3, u = idx2 & 7;
                const uint32_t doff = (uint32_t)(r * 128 + ((u ^ (r & 7)) << 4));
                CP16(stg + 16384u + doff, gB + (size_t)r * D_ + k0 + u * 4);
            }
        }
    };

    issueK1(sb,                0);  CPCOMMIT();
    issueK1(sb + K1_STAGE,     32); CPCOMMIT();
    issueK1(sb + 2 * K1_STAGE, 64); CPCOMMIT();

    const uint32_t aOff = (uint32_t)((wm * 32 + g) * 128);
    const uint32_t bOff = 16384u + (uint32_t)((wn * 64 + g) * 128);

    #pragma unroll 1
    for (int c = 0; c < 16; c++) {
        CPWAIT2();
        __syncthreads();
        const uint32_t st = sb + (uint32_t)(c & 3) * K1_STAGE;
        #pragma unroll
        for (int kk = 0; kk < 4; kk++) {
            const uint32_t o0 = ((uint32_t)((2 * kk)     ^ g) << 4) + t * 4;
            const uint32_t o1 = ((uint32_t)((2 * kk + 1) ^ g) << 4) + t * 4;
            uint32_t a[2][4];
            #pragma unroll
            for (int mi = 0; mi < 2; mi++) {
                const uint32_t ar = st + aOff + (uint32_t)(mi * 2048);
                a[mi][0] = lds32(ar + o0);
                a[mi][1] = lds32(ar + 1024 + o0);
                a[mi][2] = lds32(ar + o1);
                a[mi][3] = lds32(ar + 1024 + o1);
            }
            #pragma unroll
            for (int ni = 0; ni < 8; ni++) {
                const uint32_t br = st + bOff + (uint32_t)(ni * 1024);
                const uint32_t b0 = lds32(br + o0);
                const uint32_t b1 = lds32(br + o1);
                mma_tf32(cc[0][ni], a[0], b0, b1);
                mma_tf32(cc[1][ni], a[1], b0, b1);
            }
        }
        if (c + 3 < 16)
            issueK1(sb + (uint32_t)((c + 3) & 3) * K1_STAGE, (c + 3) * 32);
        CPCOMMIT();
    }

    // Fused epilogue: relu(+b1) + old_x, dot W2, shfl-reduce over t, atomics.
    #pragma unroll
    for (int mi = 0; mi < 2; mi++) {
        #pragma unroll
        for (int h = 0; h < 2; h++) {
            const int row = row0 + wm * 32 + mi * 16 + h * 8 + g;
            const float* oxr = old_x + (size_t)row * D_;
            float acc = 0.f;
            #pragma unroll
            for (int ni = 0; ni < 8; ni++) {
                const int e = n0 + wn * 64 + ni * 8 + 2 * t;
                float2 b1v = *reinterpret_cast<const float2*>(b1l + e);
                float2 w2v = *reinterpret_cast<const float2*>(W2l + e);
                float2 oxv = *reinterpret_cast<const float2*>(oxr + e);
                acc += (fmaxf(cc[mi][ni][2 * h]     + b1v.x, 0.f) + oxv.x) * w2v.x
                     + (fmaxf(cc[mi][ni][2 * h + 1] + b1v.y, 0.f) + oxv.y) * w2v.y;
            }
            acc += __shfl_xor_sync(0xFFFFFFFFu, acc, 1);
            acc += __shfl_xor_sync(0xFFFFFFFFu, acc, 2);
            if (t == 0) atomicAdd(&g_logit[row], acc);
        }
    }
}

// ---------------------------------------------------------------------------
// Kernel 2: fused dual GEMM  out = (x@Ws^T)*(1-gv) + (x@Wl^T)*gv   (unchanged R8)
// ---------------------------------------------------------------------------
#define STAGE_D   49152
#define SMEM_DUAL (STAGE_D * 4)

__global__ void __launch_bounds__(512, 1) k2_fused(
    const float* __restrict__ x, const int* __restrict__ lang,
    const float* __restrict__ gb2, float* __restrict__ out)
{
    extern __shared__ __align__(128) char dsm[];
    const uint32_t sb = smem_u32(dsm);
    const int tid  = threadIdx.x;
    const int wid  = tid >> 5, lane = tid & 31;
    const int g    = lane >> 2, t = lane & 3;
    const int wm   = wid & 3,  wn  = wid >> 2;
    const int nt   = blockIdx.x;
    const int rt   = blockIdx.y;
    const int row0 = rt * 128;
    const int n0   = nt * 128;
    const int lg   = lang[rt >> 4];

    const float* gA = x + (size_t)row0 * D_;
    const float* gS = reinterpret_cast<const float*>(g_Ws) + (size_t)n0 * D_;
    const float* gL = reinterpret_cast<const float*>(g_Wl)
                    + (size_t)lg * D_ * D_ + (size_t)n0 * D_;
    const float bb2 = gb2[lg];

    float cs[2][4][4], cl[2][4][4];
    #pragma unroll
    for (int mi = 0; mi < 2; mi++)
        #pragma unroll
        for (int ni = 0; ni < 4; ni++)
            #pragma unroll
            for (int r = 0; r < 4; r++) { cs[mi][ni][r] = 0.f; cl[mi][ni][r] = 0.f; }

    auto issue3 = [&](uint32_t stg, int k0) {
        #pragma unroll
        for (int j = 0; j < 2; j++) {
            const int idx = tid * 2 + j;
            const int r = idx >> 3, u = idx & 7;
            const uint32_t doff = (uint32_t)(r * 128 + ((u ^ (r & 7)) << 4));
            const size_t goff = (size_t)r * D_ + k0 + u * 4;
            CP16(stg + doff,          gA + goff);
            CP16(stg + 16384u + doff, gS + goff);
            CP16(stg + 32768u + doff, gL + goff);
        }
    };

    issue3(sb,               0);  CPCOMMIT();
    issue3(sb + STAGE_D,     32); CPCOMMIT();
    issue3(sb + 2 * STAGE_D, 64); CPCOMMIT();

    const uint32_t aOff = (uint32_t)((wm * 32 + g) * 128);
    const uint32_t sOff = 16384u + (uint32_t)((wn * 32 + g) * 128);
    const uint32_t lOff = 32768u + (uint32_t)((wn * 32 + g) * 128);

    #pragma unroll 1
    for (int c = 0; c < 16; c++) {
        CPWAIT2();
        __syncthreads();
        const uint32_t st = sb + (uint32_t)(c & 3) * STAGE_D;
        #pragma unroll
        for (int kk = 0; kk < 4; kk++) {
            const uint32_t o0 = ((uint32_t)((2 * kk)     ^ g) << 4) + t * 4;
            const uint32_t o1 = ((uint32_t)((2 * kk + 1) ^ g) << 4) + t * 4;
            uint32_t a[2][4];
            #pragma unroll
            for (int mi = 0; mi < 2; mi++) {
                const uint32_t ar = st + aOff + (uint32_t)(mi * 2048);
                a[mi][0] = lds32(ar + o0);
                a[mi][1] = lds32(ar + 1024 + o0);
                a[mi][2] = lds32(ar + o1);
                a[mi][3] = lds32(ar + 1024 + o1);
            }
            #pragma unroll
            for (int ni = 0; ni < 4; ni++) {
                const uint32_t sr = st + sOff + (uint32_t)(ni * 1024);
                const uint32_t lr = st + lOff + (uint32_t)(ni * 1024);
                const uint32_t s0 = lds32(sr + o0);
                const uint32_t s1 = lds32(sr + o1);
                const uint32_t l0 = lds32(lr + o0);
                const uint32_t l1 = lds32(lr + o1);
                mma_tf32(cs[0][ni], a[0], s0, s1);
                mma_tf32(cs[1][ni], a[1], s0, s1);
                mma_tf32(cl[0][ni], a[0], l0, l1);
                mma_tf32(cl[1][ni], a[1], l0, l1);
            }
        }
        if (c + 3 < 16)
            issue3(sb + (uint32_t)((c + 3) & 3) * STAGE_D, (c + 3) * 32);
        CPCOMMIT();
    }

    #pragma unroll
    for (int mi = 0; mi < 2; mi++) {
        #pragma unroll
        for (int h = 0; h < 2; h++) {
            const int row = row0 + wm * 32 + mi * 16 + h * 8 + g;
            const float gv  = 1.f / (1.f + expf(-(g_logit[row] + bb2)));
            const float ngv = 1.f - gv;
            float* o = out + (size_t)row * D_ + n0 + wn * 32;
            #pragma unroll
            for (int ni = 0; ni < 4; ni++) {
                *reinterpret_cast<float2*>(o + ni * 8 + 2 * t) =
                    make_float2(cs[mi][ni][2 * h]     * ngv + cl[mi][ni][2 * h]     * gv,
                                cs[mi][ni][2 * h + 1] * ngv + cl[mi][ni][2 * h + 1] * gv);
            }
        }
    }
}

// ---------------------------------------------------------------------------
// launch
// ---------------------------------------------------------------------------
extern "C" void kernel_launch(void* const* d_in, const int* in_sizes, int n_in,
                              void* d_out, int out_size)
{
    const float* old_x  = (const float*)d_in[0];
    const float* x      = (const float*)d_in[1];
    const int*   lang   = (const int*)  d_in[2];
    const float* shareW = (const float*)d_in[3];
    const float* langsW = (const float*)d_in[4];
    const float* gW1    = (const float*)d_in[5];
    const float* gb1    = (const float*)d_in[6];
    const float* gW2    = (const float*)d_in[7];
    const float* gb2    = (const float*)d_in[8];
    float* out = (float*)d_out;

    cudaFuncSetAttribute(k1_gate,  cudaFuncAttributeMaxDynamicSharedMemorySize, K1_SMEM);
    cudaFuncSetAttribute(k2_fused, cudaFuncAttributeMaxDynamicSharedMemorySize, SMEM_DUAL);

    void* logit_ptr = nullptr;
    cudaGetSymbolAddress(&logit_ptr, g_logit);
    cudaMemsetAsync(logit_ptr, 0, M_TOTAL * sizeof(float));

    kconv<<<4352, 256>>>(shareW, langsW, gW1);

    k1_gate <<<dim3(2, M_TOTAL / 128), 512, K1_SMEM>>>(old_x, lang, gb1, gW2);
    k2_fused<<<dim3(D_ / 128, M_TOTAL / 128), 512, SMEM_DUAL>>>(x, lang, gb2, out);
}

// round 10
// speedup vs baseline: 1.7785x; 1.0022x over previous
#include <cuda_runtime.h>
#include <cstdint>
#include <math.h>

#define B_  32
#define S_  2048
#define D_  512
#define M_TOTAL (B_ * S_)

// Device scratch (allocation-free): gate logits + RNA-canonical tf32 weights.
__device__ float    g_logit[M_TOTAL];
__device__ uint32_t g_Ws[D_ * D_];
__device__ uint32_t g_Wl[8 * D_ * D_];
__device__ uint32_t g_W1[8 * D_ * D_];

// ---------------------------------------------------------------------------
// helpers
// ---------------------------------------------------------------------------
__device__ __forceinline__ uint32_t smem_u32(const void* p) {
    uint32_t a;
    asm("{ .reg .u64 t; cvta.to.shared.u64 t, %1; cvt.u32.u64 %0, t; }" : "=r"(a) : "l"(p));
    return a;
}
__device__ __forceinline__ uint32_t f2tf32(float f) {
    uint32_t u; asm("cvt.rna.tf32.f32 %0, %1;" : "=r"(u) : "f"(f)); return u;
}
__device__ __forceinline__ void mma_tf32(float* c, const uint32_t* a, uint32_t b0, uint32_t b1) {
    asm volatile(
        "mma.sync.aligned.m16n8k8.row.col.f32.tf32.tf32.f32 "
        "{%0,%1,%2,%3}, {%4,%5,%6,%7}, {%8,%9}, {%0,%1,%2,%3};"
        : "+f"(c[0]), "+f"(c[1]), "+f"(c[2]), "+f"(c[3])
        : "r"(a[0]), "r"(a[1]), "r"(a[2]), "r"(a[3]), "r"(b0), "r"(b1));
}
__device__ __forceinline__ uint32_t lds32(uint32_t a) {
    uint32_t v; asm volatile("ld.shared.b32 %0, [%1];" : "=r"(v) : "r"(a)); return v;
}

#define CP16(d, s)  asm volatile("cp.async.cg.shared.global [%0], [%1], 16;" :: "r"(d), "l"(s))
#define CPCOMMIT()  asm volatile("cp.async.commit_group;" ::: "memory")
#define CPWAIT2()   asm volatile("cp.async.wait_group 2;" ::: "memory")

// ---------------------------------------------------------------------------
// Weight conversion: fp32 -> RNA-canonical tf32 bit patterns (one pass).
// ---------------------------------------------------------------------------
__global__ void __launch_bounds__(256) kconv(
    const float* __restrict__ Ws, const float* __restrict__ Wl,
    const float* __restrict__ W1)
{
    int i = blockIdx.x * 256 + threadIdx.x;
    const int NWS = D_ * D_ / 4;
    const int NWL = 8 * D_ * D_ / 4;
    const float4* src; uint4* dst; int j;
    if (i < NWS)            { src = (const float4*)Ws; dst = (uint4*)g_Ws; j = i; }
    else if (i < NWS + NWL) { src = (const float4*)Wl; dst = (uint4*)g_Wl; j = i - NWS; }
    else                    { src = (const float4*)W1; dst = (uint4*)g_W1; j = i - NWS - NWL; }
    float4 v = src[j];
    uint4 o;
    o.x = f2tf32(v.x); o.y = f2tf32(v.y); o.z = f2tf32(v.z); o.w = f2tf32(v.w);
    dst[j] = o;
}

// ---------------------------------------------------------------------------
// Kernel 1: gate GEMM (old_x @ W1^T) + fused relu/+old_x/.W2 -> atomic logits.
// CTA tile 128x256, warp tile 32x64, occ 1, 4-stage cp.async. (AT TENSOR
// FLOOR as of R9 -- unchanged.)
// ---------------------------------------------------------------------------
#define K1_STAGE 49152
#define K1_SMEM  (K1_STAGE * 4)

__global__ void __launch_bounds__(512, 1) k1_gate(
    const float* __restrict__ old_x, const int* __restrict__ lang,
    const float* __restrict__ gb1,  const float* __restrict__ gW2)
{
    extern __shared__ __align__(128) char dsm[];
    const uint32_t sb = smem_u32(dsm);
    const int tid  = threadIdx.x;
    const int wid  = tid >> 5, lane = tid & 31;
    const int g    = lane >> 2, t = lane & 3;
    const int wm   = wid & 3,  wn  = wid >> 2;
    const int nt   = blockIdx.x;
    const int rt   = blockIdx.y;
    const int row0 = rt * 128;
    const int n0   = nt * 256;
    const int lg   = lang[rt >> 4];

    const float* gA = old_x + (size_t)row0 * D_;
    const float* gB = reinterpret_cast<const float*>(g_W1)
                    + (size_t)lg * D_ * D_ + (size_t)n0 * D_;
    const float* b1l = gb1 + lg * D_;
    const float* W2l = gW2 + lg * D_;

    float cc[2][8][4];
    #pragma unroll
    for (int mi = 0; mi < 2; mi++)
        #pragma unroll
        for (int ni = 0; ni < 8; ni++)
            #pragma unroll
            for (int r = 0; r < 4; r++) cc[mi][ni][r] = 0.f;

    auto issueK1 = [&](uint32_t stg, int k0) {
        #pragma unroll
        for (int j = 0; j < 6; j++) {
            const int idx = j * 512 + tid;
            if (idx < 1024) {
                const int r = idx >> 3, u = idx & 7;
                const uint32_t doff = (uint32_t)(r * 128 + ((u ^ (r & 7)) << 4));
                CP16(stg + doff, gA + (size_t)r * D_ + k0 + u * 4);
            } else {
                const int idx2 = idx - 1024;
                const int r = idx2 >> 3, u = idx2 & 7;
                const uint32_t doff = (uint32_t)(r * 128 + ((u ^ (r & 7)) << 4));
                CP16(stg + 16384u + doff, gB + (size_t)r * D_ + k0 + u * 4);
            }
        }
    };

    issueK1(sb,                0);  CPCOMMIT();
    issueK1(sb + K1_STAGE,     32); CPCOMMIT();
    issueK1(sb + 2 * K1_STAGE, 64); CPCOMMIT();

    const uint32_t aOff = (uint32_t)((wm * 32 + g) * 128);
    const uint32_t bOff = 16384u + (uint32_t)((wn * 64 + g) * 128);

    #pragma unroll 1
    for (int c = 0; c < 16; c++) {
        CPWAIT2();
        __syncthreads();
        const uint32_t st = sb + (uint32_t)(c & 3) * K1_STAGE;
        #pragma unroll
        for (int kk = 0; kk < 4; kk++) {
            const uint32_t o0 = ((uint32_t)((2 * kk)     ^ g) << 4) + t * 4;
            const uint32_t o1 = ((uint32_t)((2 * kk + 1) ^ g) << 4) + t * 4;
            uint32_t a[2][4];
            #pragma unroll
            for (int mi = 0; mi < 2; mi++) {
                const uint32_t ar = st + aOff + (uint32_t)(mi * 2048);
                a[mi][0] = lds32(ar + o0);
                a[mi][1] = lds32(ar + 1024 + o0);
                a[mi][2] = lds32(ar + o1);
                a[mi][3] = lds32(ar + 1024 + o1);
            }
            #pragma unroll
            for (int ni = 0; ni < 8; ni++) {
                const uint32_t br = st + bOff + (uint32_t)(ni * 1024);
                const uint32_t b0 = lds32(br + o0);
                const uint32_t b1 = lds32(br + o1);
                mma_tf32(cc[0][ni], a[0], b0, b1);
                mma_tf32(cc[1][ni], a[1], b0, b1);
            }
        }
        if (c + 3 < 16)
            issueK1(sb + (uint32_t)((c + 3) & 3) * K1_STAGE, (c + 3) * 32);
        CPCOMMIT();
    }

    #pragma unroll
    for (int mi = 0; mi < 2; mi++) {
        #pragma unroll
        for (int h = 0; h < 2; h++) {
            const int row = row0 + wm * 32 + mi * 16 + h * 8 + g;
            const float* oxr = old_x + (size_t)row * D_;
            float acc = 0.f;
            #pragma unroll
            for (int ni = 0; ni < 8; ni++) {
                const int e = n0 + wn * 64 + ni * 8 + 2 * t;
                float2 b1v = *reinterpret_cast<const float2*>(b1l + e);
                float2 w2v = *reinterpret_cast<const float2*>(W2l + e);
                float2 oxv = *reinterpret_cast<const float2*>(oxr + e);
                acc += (fmaxf(cc[mi][ni][2 * h]     + b1v.x, 0.f) + oxv.x) * w2v.x
                     + (fmaxf(cc[mi][ni][2 * h + 1] + b1v.y, 0.f) + oxv.y) * w2v.y;
            }
            acc += __shfl_xor_sync(0xFFFFFFFFu, acc, 1);
            acc += __shfl_xor_sync(0xFFFFFFFFu, acc, 2);
            if (t == 0) atomicAdd(&g_logit[row], acc);
        }
    }
}

// ---------------------------------------------------------------------------
// Kernel 2: fused dual GEMM  out = (x@Ws^T)*(1-gv) + (x@Wl^T)*gv.
// NEW: fragment double-buffering across kk -- load kk+1's A/Bs/Bl fragments
// while kk's 16 MMAs issue (hides the 29-cyc LDS latency that was exposed).
// ---------------------------------------------------------------------------
#define STAGE_D   49152
#define SMEM_DUAL (STAGE_D * 4)

__global__ void __launch_bounds__(512, 1) k2_fused(
    const float* __restrict__ x, const int* __restrict__ lang,
    const float* __restrict__ gb2, float* __restrict__ out)
{
    extern __shared__ __align__(128) char dsm[];
    const uint32_t sb = smem_u32(dsm);
    const int tid  = threadIdx.x;
    const int wid  = tid >> 5, lane = tid & 31;
    const int g    = lane >> 2, t = lane & 3;
    const int wm   = wid & 3,  wn  = wid >> 2;
    const int nt   = blockIdx.x;
    const int rt   = blockIdx.y;
    const int row0 = rt * 128;
    const int n0   = nt * 128;
    const int lg   = lang[rt >> 4];

    const float* gA = x + (size_t)row0 * D_;
    const float* gS = reinterpret_cast<const float*>(g_Ws) + (size_t)n0 * D_;
    const float* gL = reinterpret_cast<const float*>(g_Wl)
                    + (size_t)lg * D_ * D_ + (size_t)n0 * D_;
    const float bb2 = gb2[lg];

    float cs[2][4][4], cl[2][4][4];
    #pragma unroll
    for (int mi = 0; mi < 2; mi++)
        #pragma unroll
        for (int ni = 0; ni < 4; ni++)
            #pragma unroll
            for (int r = 0; r < 4; r++) { cs[mi][ni][r] = 0.f; cl[mi][ni][r] = 0.f; }

    auto issue3 = [&](uint32_t stg, int k0) {
        #pragma unroll
        for (int j = 0; j < 2; j++) {
            const int idx = tid * 2 + j;
            const int r = idx >> 3, u = idx & 7;
            const uint32_t doff = (uint32_t)(r * 128 + ((u ^ (r & 7)) << 4));
            const size_t goff = (size_t)r * D_ + k0 + u * 4;
            CP16(stg + doff,          gA + goff);
            CP16(stg + 16384u + doff, gS + goff);
            CP16(stg + 32768u + doff, gL + goff);
        }
    };

    issue3(sb,               0);  CPCOMMIT();
    issue3(sb + STAGE_D,     32); CPCOMMIT();
    issue3(sb + 2 * STAGE_D, 64); CPCOMMIT();

    const uint32_t aOff = (uint32_t)((wm * 32 + g) * 128);
    const uint32_t sOff = 16384u + (uint32_t)((wn * 32 + g) * 128);
    const uint32_t lOff = 32768u + (uint32_t)((wn * 32 + g) * 128);

    // Double-buffered fragment registers.
    uint32_t fa[2][2][4];        // [buf][mi][4]
    uint32_t fs[2][4][2];        // [buf][ni][2]
    uint32_t fl[2][4][2];

    #pragma unroll 1
    for (int c = 0; c < 16; c++) {
        CPWAIT2();
        __syncthreads();
        const uint32_t st = sb + (uint32_t)(c & 3) * STAGE_D;
        const uint32_t aBase = st + aOff;
        const uint32_t sBase = st + sOff;
        const uint32_t lBase = st + lOff;

        // preload kk=0 fragments into buf 0
        {
            const uint32_t o0 = ((uint32_t)(0 ^ g) << 4) + t * 4;
            const uint32_t o1 = ((uint32_t)(1 ^ g) << 4) + t * 4;
            #pragma unroll
            for (int mi = 0; mi < 2; mi++) {
                const uint32_t ar = aBase + (uint32_t)(mi * 2048);
                fa[0][mi][0] = lds32(ar + o0);
                fa[0][mi][1] = lds32(ar + 1024 + o0);
                fa[0][mi][2] = lds32(ar + o1);
                fa[0][mi][3] = lds32(ar + 1024 + o1);
            }
            #pragma unroll
            for (int ni = 0; ni < 4; ni++) {
                const uint32_t sr = sBase + (uint32_t)(ni * 1024);
                const uint32_t lr = lBase + (uint32_t)(ni * 1024);
                fs[0][ni][0] = lds32(sr + o0);
                fs[0][ni][1] = lds32(sr + o1);
                fl[0][ni][0] = lds32(lr + o0);
                fl[0][ni][1] = lds32(lr + o1);
            }
        }

        #pragma unroll
        for (int kk = 0; kk < 4; kk++) {
            const int cur = kk & 1, nxt = cur ^ 1;
            if (kk < 3) {
                const uint32_t o0 = ((uint32_t)((2 * (kk + 1))     ^ g) << 4) + t * 4;
                const uint32_t o1 = ((uint32_t)((2 * (kk + 1) + 1) ^ g) << 4) + t * 4;
                #pragma unroll
                for (int mi = 0; mi < 2; mi++) {
                    const uint32_t ar = aBase + (uint32_t)(mi * 2048);
                    fa[nxt][mi][0] = lds32(ar + o0);
                    fa[nxt][mi][1] = lds32(ar + 1024 + o0);
                    fa[nxt][mi][2] = lds32(ar + o1);
                    fa[nxt][mi][3] = lds32(ar + 1024 + o1);
                }
                #pragma unroll
                for (int ni = 0; ni < 4; ni++) {
                    const uint32_t sr = sBase + (uint32_t)(ni * 1024);
                    const uint32_t lr = lBase + (uint32_t)(ni * 1024);
                    fs[nxt][ni][0] = lds32(sr + o0);
                    fs[nxt][ni][1] = lds32(sr + o1);
                    fl[nxt][ni][0] = lds32(lr + o0);
                    fl[nxt][ni][1] = lds32(lr + o1);
                }
            }
            #pragma unroll
            for (int ni = 0; ni < 4; ni++) {
                mma_tf32(cs[0][ni], fa[cur][0], fs[cur][ni][0], fs[cur][ni][1]);
                mma_tf32(cs[1][ni], fa[cur][1], fs[cur][ni][0], fs[cur][ni][1]);
                mma_tf32(cl[0][ni], fa[cur][0], fl[cur][ni][0], fl[cur][ni][1]);
                mma_tf32(cl[1][ni], fa[cur][1], fl[cur][ni][0], fl[cur][ni][1]);
            }
        }
        if (c + 3 < 16)
            issue3(sb + (uint32_t)((c + 3) & 3) * STAGE_D, (c + 3) * 32);
        CPCOMMIT();
    }

    #pragma unroll
    for (int mi = 0; mi < 2; mi++) {
        #pragma unroll
        for (int h = 0; h < 2; h++) {
            const int row = row0 + wm * 32 + mi * 16 + h * 8 + g;
            const float gv  = 1.f / (1.f + expf(-(g_logit[row] + bb2)));
            const float ngv = 1.f - gv;
            float* o = out + (size_t)row * D_ + n0 + wn * 32;
            #pragma unroll
            for (int ni = 0; ni < 4; ni++) {
                *reinterpret_cast<float2*>(o + ni * 8 + 2 * t) =
                    make_float2(cs[mi][ni][2 * h]     * ngv + cl[mi][ni][2 * h]     * gv,
                                cs[mi][ni][2 * h + 1] * ngv + cl[mi][ni][2 * h + 1] * gv);
            }
        }
    }
}

// ---------------------------------------------------------------------------
// launch
// ---------------------------------------------------------------------------
extern "C" void kernel_launch(void* const* d_in, const int* in_sizes, int n_in,
                              void* d_out, int out_size)
{
    const float* old_x  = (const float*)d_in[0];
    const float* x      = (const float*)d_in[1];
    const int*   lang   = (const int*)  d_in[2];
    const float* shareW = (const float*)d_in[3];
    const float* langsW = (const float*)d_in[4];
    const float* gW1    = (const float*)d_in[5];
    const float* gb1    = (const float*)d_in[6];
    const float* gW2    = (const float*)d_in[7];
    const float* gb2    = (const float*)d_in[8];
    float* out = (float*)d_out;

    cudaFuncSetAttribute(k1_gate,  cudaFuncAttributeMaxDynamicSharedMemorySize, K1_SMEM);
    cudaFuncSetAttribute(k2_fused, cudaFuncAttributeMaxDynamicSharedMemorySize, SMEM_DUAL);

    void* logit_ptr = nullptr;
    cudaGetSymbolAddress(&logit_ptr, g_logit);
    cudaMemsetAsync(logit_ptr, 0, M_TOTAL * sizeof(float));

    kconv<<<4352, 256>>>(shareW, langsW, gW1);

    k1_gate <<<dim3(2, M_TOTAL / 128), 512, K1_SMEM>>>(old_x, lang, gb1, gW2);
    k2_fused<<<dim3(D_ / 128, M_TOTAL / 128), 512, SMEM_DUAL>>>(x, lang, gb2, out);
}

// round 11
// speedup vs baseline: 1.9603x; 1.1022x over previous
#include <cuda_runtime.h>
#include <cstdint>
#include <math.h>

#define B_  32
#define S_  2048
#define D_  512
#define M_TOTAL (B_ * S_)

// Device scratch (allocation-free): gate logits + converted weights.
__device__ float    g_logit[M_TOTAL];
__device__ uint32_t g_Ws[D_ * D_];            // tf32 (RNA) share weights
__device__ uint32_t g_Wl[8 * D_ * D_];        // tf32 (RNA) lang weights
__device__ uint32_t g_W1h[8 * D_ * D_ / 2];   // bf16-packed gate weights

// ---------------------------------------------------------------------------
// helpers
// ---------------------------------------------------------------------------
__device__ __forceinline__ uint32_t smem_u32(const void* p) {
    uint32_t a;
    asm("{ .reg .u64 t; cvta.to.shared.u64 t, %1; cvt.u32.u64 %0, t; }" : "=r"(a) : "l"(p));
    return a;
}
__device__ __forceinline__ uint32_t f2tf32(float f) {
    uint32_t u; asm("cvt.rna.tf32.f32 %0, %1;" : "=r"(u) : "f"(f)); return u;
}
__device__ __forceinline__ uint32_t bf16x2(float hi, float lo) {
    uint32_t r; asm("cvt.rn.bf16x2.f32 %0, %1, %2;" : "=r"(r) : "f"(hi), "f"(lo)); return r;
}
__device__ __forceinline__ void mma_tf32(float* c, const uint32_t* a, uint32_t b0, uint32_t b1) {
    asm volatile(
        "mma.sync.aligned.m16n8k8.row.col.f32.tf32.tf32.f32 "
        "{%0,%1,%2,%3}, {%4,%5,%6,%7}, {%8,%9}, {%0,%1,%2,%3};"
        : "+f"(c[0]), "+f"(c[1]), "+f"(c[2]), "+f"(c[3])
        : "r"(a[0]), "r"(a[1]), "r"(a[2]), "r"(a[3]), "r"(b0), "r"(b1));
}
__device__ __forceinline__ void mma_bf16(float* c, const uint32_t* a, uint32_t b0, uint32_t b1) {
    asm volatile(
        "mma.sync.aligned.m16n8k16.row.col.f32.bf16.bf16.f32 "
        "{%0,%1,%2,%3}, {%4,%5,%6,%7}, {%8,%9}, {%0,%1,%2,%3};"
        : "+f"(c[0]), "+f"(c[1]), "+f"(c[2]), "+f"(c[3])
        : "r"(a[0]), "r"(a[1]), "r"(a[2]), "r"(a[3]), "r"(b0), "r"(b1));
}
__device__ __forceinline__ uint32_t lds32(uint32_t a) {
    uint32_t v; asm volatile("ld.shared.b32 %0, [%1];" : "=r"(v) : "r"(a)); return v;
}
__device__ __forceinline__ void sts128(uint32_t a, uint32_t x, uint32_t y, uint32_t z, uint32_t w) {
    asm volatile("st.shared.v4.b32 [%0], {%1,%2,%3,%4};"
                 :: "r"(a), "r"(x), "r"(y), "r"(z), "r"(w) : "memory");
}

#define CP16(d, s)  asm volatile("cp.async.cg.shared.global [%0], [%1], 16;" :: "r"(d), "l"(s))
#define CPCOMMIT()  asm volatile("cp.async.commit_group;" ::: "memory")
#define CPWAIT2()   asm volatile("cp.async.wait_group 2;" ::: "memory")

// ---------------------------------------------------------------------------
// Weight conversion: Ws/Wl -> RNA tf32 bits; W1 -> packed bf16.
// ---------------------------------------------------------------------------
__global__ void __launch_bounds__(256) kconv(
    const float* __restrict__ Ws, const float* __restrict__ Wl,
    const float* __restrict__ W1)
{
    int i = blockIdx.x * 256 + threadIdx.x;
    const int NWS = D_ * D_ / 4;
    const int NWL = 8 * D_ * D_ / 4;
    if (i < NWS) {
        float4 v = reinterpret_cast<const float4*>(Ws)[i];
        uint4 o; o.x = f2tf32(v.x); o.y = f2tf32(v.y); o.z = f2tf32(v.z); o.w = f2tf32(v.w);
        reinterpret_cast<uint4*>(g_Ws)[i] = o;
    } else if (i < NWS + NWL) {
        int j = i - NWS;
        float4 v = reinterpret_cast<const float4*>(Wl)[j];
        uint4 o; o.x = f2tf32(v.x); o.y = f2tf32(v.y); o.z = f2tf32(v.z); o.w = f2tf32(v.w);
        reinterpret_cast<uint4*>(g_Wl)[j] = o;
    } else {
        int j = i - NWS - NWL;
        float4 v = reinterpret_cast<const float4*>(W1)[j];
        uint2 o; o.x = bf16x2(v.y, v.x); o.y = bf16x2(v.w, v.z);
        reinterpret_cast<uint2*>(g_W1h)[j] = o;
    }
}

// ---------------------------------------------------------------------------
// Kernel 1: gate GEMM in BF16 (old_x @ W1^T) + fused relu/+old_x/.W2 epilogue.
// CTA tile 128x256, warp grid 4m x 4n, warp tile 32x64, occ 1.
// A: old_x fp32 LDG -> cvt bf16 -> STS (2-deep register prefetch, 2 smem bufs)
// B: pre-converted bf16 weights via 4-stage cp.async.
// BF16 smem: row = 32 bf16 = 16 u32 (64B); u32 slot u stored at u^(c<<2),
// c = (row>>1)&3 -> conflict-free frag lds32 and STS.128 (verified).
// ---------------------------------------------------------------------------
#define K1_A_STG  8192
#define K1_B_STG  16384
#define K1_SMEM   (K1_A_STG * 2 + K1_B_STG * 4)   // 80KB

__global__ void __launch_bounds__(512, 1) k1_gate(
    const float* __restrict__ old_x, const int* __restrict__ lang,
    const float* __restrict__ gb1,  const float* __restrict__ gW2)
{
    extern __shared__ __align__(128) char dsm[];
    const uint32_t sbA = smem_u32(dsm);
    const uint32_t sbB = sbA + K1_A_STG * 2;

    const int tid  = threadIdx.x;
    const int wid  = tid >> 5, lane = tid & 31;
    const int g    = lane >> 2, t = lane & 3;
    const int wm   = wid & 3,  wn  = wid >> 2;
    const int nt   = blockIdx.x;
    const int rt   = blockIdx.y;
    const int row0 = rt * 128;
    const int n0   = nt * 256;
    const int lg   = lang[rt >> 4];

    const float* gA = old_x + (size_t)row0 * D_;
    const float* b1l = gb1 + lg * D_;
    const float* W2l = gW2 + lg * D_;

    float cc[2][8][4];
    #pragma unroll
    for (int mi = 0; mi < 2; mi++)
        #pragma unroll
        for (int ni = 0; ni < 8; ni++)
            #pragma unroll
            for (int r = 0; r < 4; r++) cc[mi][ni][r] = 0.f;

    // ---- A staging: thread owns (row ar_, 8-col group agi_) = 8 floats/chunk
    const int ar_ = tid >> 2, agi_ = tid & 3;
    const uint32_t aDst = sbA + (uint32_t)(ar_ * 64 + ((agi_ ^ ((ar_ >> 1) & 3)) << 4));
    const float* aSrc = gA + (size_t)ar_ * D_ + agi_ * 8;
    float af[8];

    auto ldgA = [&](int c) {
        const float4* p = reinterpret_cast<const float4*>(aSrc + c * 32);
        float4 v0 = __ldg(p), v1 = __ldg(p + 1);
        af[0] = v0.x; af[1] = v0.y; af[2] = v0.z; af[3] = v0.w;
        af[4] = v1.x; af[5] = v1.y; af[6] = v1.z; af[7] = v1.w;
    };
    auto stsA = [&](int c) {
        sts128(aDst + (uint32_t)((c & 1) * K1_A_STG),
               bf16x2(af[1], af[0]), bf16x2(af[3], af[2]),
               bf16x2(af[5], af[4]), bf16x2(af[7], af[6]));
    };
    // ---- B staging: thread covers 2 of 1024 16B units (n-row, 4 u32 group)
    const size_t w1Base = ((size_t)lg * 512 + n0) << 8;   // u32 offset, 256 u32/row
    auto issueB = [&](int c) {
        const uint32_t stg = sbB + (uint32_t)((c & 3) * K1_B_STG);
        #pragma unroll
        for (int j = 0; j < 2; j++) {
            const int idx = tid * 2 + j;
            const int n = idx >> 2, gi = idx & 3;
            const uint32_t doff = (uint32_t)(n * 64 + ((gi ^ ((n >> 1) & 3)) << 4));
            const uint32_t* src = g_W1h + w1Base + (size_t)n * 256 + c * 16 + gi * 4;
            CP16(stg + doff, src);
        }
    };

    // prologue
    ldgA(0); stsA(0);
    issueB(0); CPCOMMIT();
    issueB(1); CPCOMMIT();
    issueB(2); CPCOMMIT();
    ldgA(1);

    const uint32_t aBase = sbA + (uint32_t)((wm * 32 + g) * 64);
    const uint32_t bBase = sbB + (uint32_t)((wn * 64 + g) * 64);
    const uint32_t cA = (uint32_t)(((g >> 1) & 3) << 2);

    #pragma unroll 1
    for (int c = 0; c < 16; c++) {
        CPWAIT2();
        __syncthreads();
        const uint32_t stA = aBase + (uint32_t)((c & 1) * K1_A_STG);
        const uint32_t stB = bBase + (uint32_t)((c & 3) * K1_B_STG);
        #pragma unroll
        for (int s = 0; s < 2; s++) {
            const uint32_t o0 = (((uint32_t)(8 * s + t)) ^ cA) << 2;
            const uint32_t o1 = o0 ^ 16;
            uint32_t a[2][4];
            #pragma unroll
            for (int mi = 0; mi < 2; mi++) {
                const uint32_t ar = stA + (uint32_t)(mi * 1024);
                a[mi][0] = lds32(ar + o0);
                a[mi][1] = lds32(ar + 512 + o0);
                a[mi][2] = lds32(ar + o1);
                a[mi][3] = lds32(ar + 512 + o1);
            }
            #pragma unroll
            for (int ni = 0; ni < 8; ni++) {
                const uint32_t br = stB + (uint32_t)(ni * 512);
                const uint32_t b0 = lds32(br + o0);
                const uint32_t b1 = lds32(br + o1);
                mma_bf16(cc[0][ni], a[0], b0, b1);
                mma_bf16(cc[1][ni], a[1], b0, b1);
            }
        }
        if (c + 1 < 16) stsA(c + 1);
        if (c + 2 < 16) ldgA(c + 2);
        if (c + 3 < 16) issueB(c + 3);
        CPCOMMIT();
    }

    // Fused epilogue (fp32): relu(+b1)+old_x, dot W2, shfl-reduce, atomics.
    #pragma unroll
    for (int mi = 0; mi < 2; mi++) {
        #pragma unroll
        for (int h = 0; h < 2; h++) {
            const int row = row0 + wm * 32 + mi * 16 + h * 8 + g;
            const float* oxr = old_x + (size_t)row * D_;
            float acc = 0.f;
            #pragma unroll
            for (int ni = 0; ni < 8; ni++) {
                const int e = n0 + wn * 64 + ni * 8 + 2 * t;
                float2 b1v = *reinterpret_cast<const float2*>(b1l + e);
                float2 w2v = *reinterpret_cast<const float2*>(W2l + e);
                float2 oxv = *reinterpret_cast<const float2*>(oxr + e);
                acc += (fmaxf(cc[mi][ni][2 * h]     + b1v.x, 0.f) + oxv.x) * w2v.x
                     + (fmaxf(cc[mi][ni][2 * h + 1] + b1v.y, 0.f) + oxv.y) * w2v.y;
            }
            acc += __shfl_xor_sync(0xFFFFFFFFu, acc, 1);
            acc += __shfl_xor_sync(0xFFFFFFFFu, acc, 2);
            if (t == 0) atomicAdd(&g_logit[row], acc);
        }
    }
}

// ---------------------------------------------------------------------------
// Kernel 2: fused dual GEMM (tf32, unchanged from R10).
// ---------------------------------------------------------------------------
#define STAGE_D   49152
#define SMEM_DUAL (STAGE_D * 4)

__global__ void __launch_bounds__(512, 1) k2_fused(
    const float* __restrict__ x, const int* __restrict__ lang,
    const float* __restrict__ gb2, float* __restrict__ out)
{
    extern __shared__ __align__(128) char dsm[];
    const uint32_t sb = smem_u32(dsm);
    const int tid  = threadIdx.x;
    const int wid  = tid >> 5, lane = tid & 31;
    const int g    = lane >> 2, t = lane & 3;
    const int wm   = wid & 3,  wn  = wid >> 2;
    const int nt   = blockIdx.x;
    const int rt   = blockIdx.y;
    const int row0 = rt * 128;
    const int n0   = nt * 128;
    const int lg   = lang[rt >> 4];

    const float* gA = x + (size_t)row0 * D_;
    const float* gS = reinterpret_cast<const float*>(g_Ws) + (size_t)n0 * D_;
    const float* gL = reinterpret_cast<const float*>(g_Wl)
                    + (size_t)lg * D_ * D_ + (size_t)n0 * D_;
    const float bb2 = gb2[lg];

    float cs[2][4][4], cl[2][4][4];
    #pragma unroll
    for (int mi = 0; mi < 2; mi++)
        #pragma unroll
        for (int ni = 0; ni < 4; ni++)
            #pragma unroll
            for (int r = 0; r < 4; r++) { cs[mi][ni][r] = 0.f; cl[mi][ni][r] = 0.f; }

    auto issue3 = [&](uint32_t stg, int k0) {
        #pragma unroll
        for (int j = 0; j < 2; j++) {
            const int idx = tid * 2 + j;
            const int r = idx >> 3, u = idx & 7;
            const uint32_t doff = (uint32_t)(r * 128 + ((u ^ (r & 7)) << 4));
            const size_t goff = (size_t)r * D_ + k0 + u * 4;
            CP16(stg + doff,          gA + goff);
            CP16(stg + 16384u + doff, gS + goff);
            CP16(stg + 32768u + doff, gL + goff);
        }
    };

    issue3(sb,               0);  CPCOMMIT();
    issue3(sb + STAGE_D,     32); CPCOMMIT();
    issue3(sb + 2 * STAGE_D, 64); CPCOMMIT();

    const uint32_t aOff = (uint32_t)((wm * 32 + g) * 128);
    const uint32_t sOff = 16384u + (uint32_t)((wn * 32 + g) * 128);
    const uint32_t lOff = 32768u + (uint32_t)((wn * 32 + g) * 128);

    #pragma unroll 1
    for (int c = 0; c < 16; c++) {
        CPWAIT2();
        __syncthreads();
        const uint32_t st = sb + (uint32_t)(c & 3) * STAGE_D;
        #pragma unroll
        for (int kk = 0; kk < 4; kk++) {
            const uint32_t o0 = ((uint32_t)((2 * kk)     ^ g) << 4) + t * 4;
            const uint32_t o1 = ((uint32_t)((2 * kk + 1) ^ g) << 4) + t * 4;
            uint32_t a[2][4];
            #pragma unroll
            for (int mi = 0; mi < 2; mi++) {
                const uint32_t ar = st + aOff + (uint32_t)(mi * 2048);
                a[mi][0] = lds32(ar + o0);
                a[mi][1] = lds32(ar + 1024 + o0);
                a[mi][2] = lds32(ar + o1);
                a[mi][3] = lds32(ar + 1024 + o1);
            }
            #pragma unroll
            for (int ni = 0; ni < 4; ni++) {
                const uint32_t sr = st + sOff + (uint32_t)(ni * 1024);
                const uint32_t lr = st + lOff + (uint32_t)(ni * 1024);
                const uint32_t s0 = lds32(sr + o0);
                const uint32_t s1 = lds32(sr + o1);
                const uint32_t l0 = lds32(lr + o0);
                const uint32_t l1 = lds32(lr + o1);
                mma_tf32(cs[0][ni], a[0], s0, s1);
                mma_tf32(cs[1][ni], a[1], s0, s1);
                mma_tf32(cl[0][ni], a[0], l0, l1);
                mma_tf32(cl[1][ni], a[1], l0, l1);
            }
        }
        if (c + 3 < 16)
            issue3(sb + (uint32_t)((c + 3) & 3) * STAGE_D, (c + 3) * 32);
        CPCOMMIT();
    }

    #pragma unroll
    for (int mi = 0; mi < 2; mi++) {
        #pragma unroll
        for (int h = 0; h < 2; h++) {
            const int row = row0 + wm * 32 + mi * 16 + h * 8 + g;
            const float gv  = 1.f / (1.f + expf(-(g_logit[row] + bb2)));
            const float ngv = 1.f - gv;
            float* o = out + (size_t)row * D_ + n0 + wn * 32;
            #pragma unroll
            for (int ni = 0; ni < 4; ni++) {
                *reinterpret_cast<float2*>(o + ni * 8 + 2 * t) =
                    make_float2(cs[mi][ni][2 * h]     * ngv + cl[mi][ni][2 * h]     * gv,
                                cs[mi][ni][2 * h + 1] * ngv + cl[mi][ni][2 * h + 1] * gv);
            }
        }
    }
}

// ---------------------------------------------------------------------------
// launch
// ---------------------------------------------------------------------------
extern "C" void kernel_launch(void* const* d_in, const int* in_sizes, int n_in,
                              void* d_out, int out_size)
{
    const float* old_x  = (const float*)d_in[0];
    const float* x      = (const float*)d_in[1];
    const int*   lang   = (const int*)  d_in[2];
    const float* shareW = (const float*)d_in[3];
    const float* langsW = (const float*)d_in[4];
    const float* gW1    = (const float*)d_in[5];
    const float* gb1    = (const float*)d_in[6];
    const float* gW2    = (const float*)d_in[7];
    const float* gb2    = (const float*)d_in[8];
    float* out = (float*)d_out;

    cudaFuncSetAttribute(k1_gate,  cudaFuncAttributeMaxDynamicSharedMemorySize, K1_SMEM);
    cudaFuncSetAttribute(k2_fused, cudaFuncAttributeMaxDynamicSharedMemorySize, SMEM_DUAL);

    void* logit_ptr = nullptr;
    cudaGetSymbolAddress(&logit_ptr, g_logit);
    cudaMemsetAsync(logit_ptr, 0, M_TOTAL * sizeof(float));

    kconv<<<4352, 256>>>(shareW, langsW, gW1);

    k1_gate <<<dim3(2, M_TOTAL / 128), 512, K1_SMEM>>>(old_x, lang, gb1, gW2);
    k2_fused<<<dim3(D_ / 128, M_TOTAL / 128), 512, SMEM_DUAL>>>(x, lang, gb2, out);
}

// round 12
// speedup vs baseline: 2.5876x; 1.3200x over previous
#include <cuda_runtime.h>
#include <cstdint>
#include <math.h>

#define B_  32
#define S_  2048
#define D_  512
#define M_TOTAL (B_ * S_)

// Device scratch (allocation-free): gate logits + fp16-packed weights.
__device__ float    g_logit[M_TOTAL];
__device__ uint32_t g_Wsh[D_ * D_ / 2];       // fp16 share weights
__device__ uint32_t g_Wlh[8 * D_ * D_ / 2];   // fp16 lang weights
__device__ uint32_t g_W1h[8 * D_ * D_ / 2];   // fp16 gate weights

// ---------------------------------------------------------------------------
// helpers
// ---------------------------------------------------------------------------
__device__ __forceinline__ uint32_t smem_u32(const void* p) {
    uint32_t a;
    asm("{ .reg .u64 t; cvta.to.shared.u64 t, %1; cvt.u32.u64 %0, t; }" : "=r"(a) : "l"(p));
    return a;
}
__device__ __forceinline__ uint32_t f16x2(float hi, float lo) {
    uint32_t r; asm("cvt.rn.f16x2.f32 %0, %1, %2;" : "=r"(r) : "f"(hi), "f"(lo)); return r;
}
__device__ __forceinline__ void mma_f16(float* c, const uint32_t* a, uint32_t b0, uint32_t b1) {
    asm volatile(
        "mma.sync.aligned.m16n8k16.row.col.f32.f16.f16.f32 "
        "{%0,%1,%2,%3}, {%4,%5,%6,%7}, {%8,%9}, {%0,%1,%2,%3};"
        : "+f"(c[0]), "+f"(c[1]), "+f"(c[2]), "+f"(c[3])
        : "r"(a[0]), "r"(a[1]), "r"(a[2]), "r"(a[3]), "r"(b0), "r"(b1));
}
__device__ __forceinline__ uint32_t lds32(uint32_t a) {
    uint32_t v; asm volatile("ld.shared.b32 %0, [%1];" : "=r"(v) : "r"(a)); return v;
}
__device__ __forceinline__ void sts128(uint32_t a, uint32_t x, uint32_t y, uint32_t z, uint32_t w) {
    asm volatile("st.shared.v4.b32 [%0], {%1,%2,%3,%4};"
                 :: "r"(a), "r"(x), "r"(y), "r"(z), "r"(w) : "memory");
}

#define CP16(d, s)  asm volatile("cp.async.cg.shared.global [%0], [%1], 16;" :: "r"(d), "l"(s))
#define CPCOMMIT()  asm volatile("cp.async.commit_group;" ::: "memory")
#define CPWAIT2()   asm volatile("cp.async.wait_group 2;" ::: "memory")

// ---------------------------------------------------------------------------
// Weight conversion: Ws/Wl/W1 -> packed fp16 (one pass).
// ---------------------------------------------------------------------------
__global__ void __launch_bounds__(256) kconv(
    const float* __restrict__ Ws, const float* __restrict__ Wl,
    const float* __restrict__ W1)
{
    int i = blockIdx.x * 256 + threadIdx.x;
    const int NWS = D_ * D_ / 4;
    const int NWL = 8 * D_ * D_ / 4;
    const float4* src; uint2* dst; int j;
    if (i < NWS)            { src = (const float4*)Ws; dst = (uint2*)g_Wsh; j = i; }
    else if (i < NWS + NWL) { src = (const float4*)Wl; dst = (uint2*)g_Wlh; j = i - NWS; }
    else                    { src = (const float4*)W1; dst = (uint2*)g_W1h; j = i - NWS - NWL; }
    float4 v = src[j];
    uint2 o; o.x = f16x2(v.y, v.x); o.y = f16x2(v.w, v.z);
    dst[j] = o;
}

// ---------------------------------------------------------------------------
// FP16 smem tile layout (proven in R11 k1):
//   row = 32 fp16 = 16 u32 units (64B); unit u of row r stored at byte
//   r*64 + ((u>>2 ^ ((r>>1)&3)) group swizzle). Fragment lds32 conflict-free.
// Fragment mapping (m16n8k16, verified): reg0 = (row g, cols 2t..2t+1),
// reg1 = row g+8 same cols, reg2/3 = cols +8 (unit ^ 4 -> byte ^ 16).
// ---------------------------------------------------------------------------

// ---------------------------------------------------------------------------
// Kernel 1: gate GEMM in FP16 (old_x @ W1^T) + fused relu/+old_x/.W2 epilogue.
// CTA tile 128x256, warp grid 4m x 4n, warp tile 32x64, occ 1. (R11 structure,
// bf16 -> fp16.)
// ---------------------------------------------------------------------------
#define K1_A_STG  8192
#define K1_B_STG  16384
#define K1_SMEM   (K1_A_STG * 2 + K1_B_STG * 4)   // 80KB

__global__ void __launch_bounds__(512, 1) k1_gate(
    const float* __restrict__ old_x, const int* __restrict__ lang,
    const float* __restrict__ gb1,  const float* __restrict__ gW2)
{
    extern __shared__ __align__(128) char dsm[];
    const uint32_t sbA = smem_u32(dsm);
    const uint32_t sbB = sbA + K1_A_STG * 2;

    const int tid  = threadIdx.x;
    const int wid  = tid >> 5, lane = tid & 31;
    const int g    = lane >> 2, t = lane & 3;
    const int wm   = wid & 3,  wn  = wid >> 2;
    const int nt   = blockIdx.x;
    const int rt   = blockIdx.y;
    const int row0 = rt * 128;
    const int n0   = nt * 256;
    const int lg   = lang[rt >> 4];

    const float* gA = old_x + (size_t)row0 * D_;
    const float* b1l = gb1 + lg * D_;
    const float* W2l = gW2 + lg * D_;

    float cc[2][8][4];
    #pragma unroll
    for (int mi = 0; mi < 2; mi++)
        #pragma unroll
        for (int ni = 0; ni < 8; ni++)
            #pragma unroll
            for (int r = 0; r < 4; r++) cc[mi][ni][r] = 0.f;

    const int ar_ = tid >> 2, agi_ = tid & 3;
    const uint32_t aDst = sbA + (uint32_t)(ar_ * 64 + ((agi_ ^ ((ar_ >> 1) & 3)) << 4));
    const float* aSrc = gA + (size_t)ar_ * D_ + agi_ * 8;
    float af[8];

    auto ldgA = [&](int c) {
        const float4* p = reinterpret_cast<const float4*>(aSrc + c * 32);
        float4 v0 = __ldg(p), v1 = __ldg(p + 1);
        af[0] = v0.x; af[1] = v0.y; af[2] = v0.z; af[3] = v0.w;
        af[4] = v1.x; af[5] = v1.y; af[6] = v1.z; af[7] = v1.w;
    };
    auto stsA = [&](int c) {
        sts128(aDst + (uint32_t)((c & 1) * K1_A_STG),
               f16x2(af[1], af[0]), f16x2(af[3], af[2]),
               f16x2(af[5], af[4]), f16x2(af[7], af[6]));
    };
    const size_t w1Base = ((size_t)lg * 512 + n0) << 8;
    auto issueB = [&](int c) {
        const uint32_t stg = sbB + (uint32_t)((c & 3) * K1_B_STG);
        #pragma unroll
        for (int j = 0; j < 2; j++) {
            const int idx = tid * 2 + j;
            const int n = idx >> 2, gi = idx & 3;
            const uint32_t doff = (uint32_t)(n * 64 + ((gi ^ ((n >> 1) & 3)) << 4));
            const uint32_t* src = g_W1h + w1Base + (size_t)n * 256 + c * 16 + gi * 4;
            CP16(stg + doff, src);
        }
    };

    ldgA(0); stsA(0);
    issueB(0); CPCOMMIT();
    issueB(1); CPCOMMIT();
    issueB(2); CPCOMMIT();
    ldgA(1);

    const uint32_t aBase = sbA + (uint32_t)((wm * 32 + g) * 64);
    const uint32_t bBase = sbB + (uint32_t)((wn * 64 + g) * 64);
    const uint32_t cA = (uint32_t)(((g >> 1) & 3) << 2);

    #pragma unroll 1
    for (int c = 0; c < 16; c++) {
        CPWAIT2();
        __syncthreads();
        const uint32_t stA = aBase + (uint32_t)((c & 1) * K1_A_STG);
        const uint32_t stB = bBase + (uint32_t)((c & 3) * K1_B_STG);
        #pragma unroll
        for (int s = 0; s < 2; s++) {
            const uint32_t o0 = (((uint32_t)(8 * s + t)) ^ cA) << 2;
            const uint32_t o1 = o0 ^ 16;
            uint32_t a[2][4];
            #pragma unroll
            for (int mi = 0; mi < 2; mi++) {
                const uint32_t ar = stA + (uint32_t)(mi * 1024);
                a[mi][0] = lds32(ar + o0);
                a[mi][1] = lds32(ar + 512 + o0);
                a[mi][2] = lds32(ar + o1);
                a[mi][3] = lds32(ar + 512 + o1);
            }
            #pragma unroll
            for (int ni = 0; ni < 8; ni++) {
                const uint32_t br = stB + (uint32_t)(ni * 512);
                const uint32_t b0 = lds32(br + o0);
                const uint32_t b1 = lds32(br + o1);
                mma_f16(cc[0][ni], a[0], b0, b1);
                mma_f16(cc[1][ni], a[1], b0, b1);
            }
        }
        if (c + 1 < 16) stsA(c + 1);
        if (c + 2 < 16) ldgA(c + 2);
        if (c + 3 < 16) issueB(c + 3);
        CPCOMMIT();
    }

    #pragma unroll
    for (int mi = 0; mi < 2; mi++) {
        #pragma unroll
        for (int h = 0; h < 2; h++) {
            const int row = row0 + wm * 32 + mi * 16 + h * 8 + g;
            const float* oxr = old_x + (size_t)row * D_;
            float acc = 0.f;
            #pragma unroll
            for (int ni = 0; ni < 8; ni++) {
                const int e = n0 + wn * 64 + ni * 8 + 2 * t;
                float2 b1v = *reinterpret_cast<const float2*>(b1l + e);
                float2 w2v = *reinterpret_cast<const float2*>(W2l + e);
                float2 oxv = *reinterpret_cast<const float2*>(oxr + e);
                acc += (fmaxf(cc[mi][ni][2 * h]     + b1v.x, 0.f) + oxv.x) * w2v.x
                     + (fmaxf(cc[mi][ni][2 * h + 1] + b1v.y, 0.f) + oxv.y) * w2v.y;
            }
            acc += __shfl_xor_sync(0xFFFFFFFFu, acc, 1);
            acc += __shfl_xor_sync(0xFFFFFFFFu, acc, 2);
            if (t == 0) atomicAdd(&g_logit[row], acc);
        }
    }
}

// ---------------------------------------------------------------------------
// Kernel 2: fused dual GEMM in FP16.  out = (x@Ws^T)*(1-gv) + (x@Wl^T)*gv.
// CTA tile 128x128, warp grid 4m x 4n, warp tile 32x32 per GEMM, occ 1.
// A (x): LDG->cvt f16->STS, 2-stage; B (Ws+Wl fp16): 4-stage cp.async.
// ---------------------------------------------------------------------------
#define K2_A_STG  8192
#define K2_B_STG  16384
#define K2_SMEM   (K2_A_STG * 2 + K2_B_STG * 4)   // 80KB

__global__ void __launch_bounds__(512, 1) k2_fused(
    const float* __restrict__ x, const int* __restrict__ lang,
    const float* __restrict__ gb2, float* __restrict__ out)
{
    extern __shared__ __align__(128) char dsm[];
    const uint32_t sbA = smem_u32(dsm);
    const uint32_t sbB = sbA + K2_A_STG * 2;

    const int tid  = threadIdx.x;
    const int wid  = tid >> 5, lane = tid & 31;
    const int g    = lane >> 2, t = lane & 3;
    const int wm   = wid & 3,  wn  = wid >> 2;
    const int nt   = blockIdx.x;
    const int rt   = blockIdx.y;
    const int row0 = rt * 128;
    const int n0   = nt * 128;
    const int lg   = lang[rt >> 4];

    const float* gA = x + (size_t)row0 * D_;
    const uint32_t* wsB = g_Wsh + (size_t)n0 * 256;
    const uint32_t* wlB = g_Wlh + ((size_t)lg * 512 + n0) * 256;
    const float bb2 = gb2[lg];

    float cs[2][4][4], cl[2][4][4];
    #pragma unroll
    for (int mi = 0; mi < 2; mi++)
        #pragma unroll
        for (int ni = 0; ni < 4; ni++)
            #pragma unroll
            for (int r = 0; r < 4; r++) { cs[mi][ni][r] = 0.f; cl[mi][ni][r] = 0.f; }

    const int ar_ = tid >> 2, agi_ = tid & 3;
    const uint32_t aDst = sbA + (uint32_t)(ar_ * 64 + ((agi_ ^ ((ar_ >> 1) & 3)) << 4));
    const float* aSrc = gA + (size_t)ar_ * D_ + agi_ * 8;
    float af[8];

    auto ldgA = [&](int c) {
        const float4* p = reinterpret_cast<const float4*>(aSrc + c * 32);
        float4 v0 = __ldg(p), v1 = __ldg(p + 1);
        af[0] = v0.x; af[1] = v0.y; af[2] = v0.z; af[3] = v0.w;
        af[4] = v1.x; af[5] = v1.y; af[6] = v1.z; af[7] = v1.w;
    };
    auto stsA = [&](int c) {
        sts128(aDst + (uint32_t)((c & 1) * K2_A_STG),
               f16x2(af[1], af[0]), f16x2(af[3], af[2]),
               f16x2(af[5], af[4]), f16x2(af[7], af[6]));
    };
    // B staging: 128 n-rows x 4 16B-units per tile; thread -> (n = tid>>2, gi = tid&3)
    const int bn_ = tid >> 2, bgi_ = tid & 3;
    const uint32_t bDoff = (uint32_t)(bn_ * 64 + ((bgi_ ^ ((bn_ >> 1) & 3)) << 4));
    auto issueB = [&](int c) {
        const uint32_t stg = sbB + (uint32_t)((c & 3) * K2_B_STG);
        const size_t soff = (size_t)bn_ * 256 + c * 16 + bgi_ * 4;
        CP16(stg + bDoff,         wsB + soff);
        CP16(stg + 8192u + bDoff, wlB + soff);
    };

    ldgA(0); stsA(0);
    issueB(0); CPCOMMIT();
    issueB(1); CPCOMMIT();
    issueB(2); CPCOMMIT();
    ldgA(1);

    const uint32_t aBase = sbA + (uint32_t)((wm * 32 + g) * 64);
    const uint32_t sBase = sbB + (uint32_t)((wn * 32 + g) * 64);
    const uint32_t cA = (uint32_t)(((g >> 1) & 3) << 2);

    #pragma unroll 1
    for (int c = 0; c < 16; c++) {
        CPWAIT2();
        __syncthreads();
        const uint32_t stA = aBase + (uint32_t)((c & 1) * K2_A_STG);
        const uint32_t stS = sBase + (uint32_t)((c & 3) * K2_B_STG);
        const uint32_t stL = stS + 8192u;
        #pragma unroll
        for (int s = 0; s < 2; s++) {
            const uint32_t o0 = (((uint32_t)(8 * s + t)) ^ cA) << 2;
            const uint32_t o1 = o0 ^ 16;
            uint32_t a[2][4];
            #pragma unroll
            for (int mi = 0; mi < 2; mi++) {
                const uint32_t ar = stA + (uint32_t)(mi * 1024);
                a[mi][0] = lds32(ar + o0);
                a[mi][1] = lds32(ar + 512 + o0);
                a[mi][2] = lds32(ar + o1);
                a[mi][3] = lds32(ar + 512 + o1);
            }
            #pragma unroll
            for (int ni = 0; ni < 4; ni++) {
                const uint32_t srS = stS + (uint32_t)(ni * 512);
                const uint32_t srL = stL + (uint32_t)(ni * 512);
                const uint32_t s0 = lds32(srS + o0);
                const uint32_t s1 = lds32(srS + o1);
                const uint32_t l0 = lds32(srL + o0);
                const uint32_t l1 = lds32(srL + o1);
                mma_f16(cs[0][ni], a[0], s0, s1);
                mma_f16(cs[1][ni], a[1], s0, s1);
                mma_f16(cl[0][ni], a[0], l0, l1);
                mma_f16(cl[1][ni], a[1], l0, l1);
            }
        }
        if (c + 1 < 16) stsA(c + 1);
        if (c + 2 < 16) ldgA(c + 2);
        if (c + 3 < 16) issueB(c + 3);
        CPCOMMIT();
    }

    #pragma unroll
    for (int mi = 0; mi < 2; mi++) {
        #pragma unroll
        for (int h = 0; h < 2; h++) {
            const int row = row0 + wm * 32 + mi * 16 + h * 8 + g;
            const float gv  = 1.f / (1.f + expf(-(g_logit[row] + bb2)));
            const float ngv = 1.f - gv;
            float* o = out + (size_t)row * D_ + n0 + wn * 32;
            #pragma unroll
            for (int ni = 0; ni < 4; ni++) {
                *reinterpret_cast<float2*>(o + ni * 8 + 2 * t) =
                    make_float2(cs[mi][ni][2 * h]     * ngv + cl[mi][ni][2 * h]     * gv,
                                cs[mi][ni][2 * h + 1] * ngv + cl[mi][ni][2 * h + 1] * gv);
            }
        }
    }
}

// ---------------------------------------------------------------------------
// launch
// ---------------------------------------------------------------------------
extern "C" void kernel_launch(void* const* d_in, const int* in_sizes, int n_in,
                              void* d_out, int out_size)
{
    const float* old_x  = (const float*)d_in[0];
    const float* x      = (const float*)d_in[1];
    const int*   lang   = (const int*)  d_in[2];
    const float* shareW = (const float*)d_in[3];
    const float* langsW = (const float*)d_in[4];
    const float* gW1    = (const float*)d_in[5];
    const float* gb1    = (const float*)d_in[6];
    const float* gW2    = (const float*)d_in[7];
    const float* gb2    = (const float*)d_in[8];
    float* out = (float*)d_out;

    cudaFuncSetAttribute(k1_gate,  cudaFuncAttributeMaxDynamicSharedMemorySize, K1_SMEM);
    cudaFuncSetAttribute(k2_fused, cudaFuncAttributeMaxDynamicSharedMemorySize, K2_SMEM);

    void* logit_ptr = nullptr;
    cudaGetSymbolAddress(&logit_ptr, g_logit);
    cudaMemsetAsync(logit_ptr, 0, M_TOTAL * sizeof(float));

    kconv<<<4352, 256>>>(shareW, langsW, gW1);

    k1_gate <<<dim3(2, M_TOTAL / 128), 512, K1_SMEM>>>(old_x, lang, gb1, gW2);
    k2_fused<<<dim3(D_ / 128, M_TOTAL / 128), 512, K2_SMEM>>>(x, lang, gb2, out);
}